// round 8
// baseline (speedup 1.0000x reference)
#include <cuda_runtime.h>
#include <cuda_bf16.h>
#include <cstdint>

// ---------------- scratch (device globals) ----------------
__device__ __align__(16) __nv_bfloat16 g_Xh[4096*1024], g_Xl[4096*1024];
__device__ __align__(16) __nv_bfloat16 g_Wh[3*1024*1024], g_Wl[3*1024*1024];
__device__ __align__(16) __nv_bfloat16 g_Qh[32*2048*64], g_Ql[32*2048*64];
__device__ __align__(16) __nv_bfloat16 g_Kh[32*2048*64], g_Kl[32*2048*64];
__device__ __align__(16) __nv_bfloat16 g_Vh[32*2048*64], g_Vl[32*2048*64];

// ---------------- helpers ----------------
__device__ __forceinline__ uint32_t smem_u32(const void* p) {
    uint32_t a;
    asm("{ .reg .u64 t; cvta.to.shared.u64 t, %1; cvt.u32.u64 %0, t; }" : "=r"(a) : "l"(p));
    return a;
}
__device__ __forceinline__ uint32_t packbf(__nv_bfloat16 a, __nv_bfloat16 b) {
    return (uint32_t)*(uint16_t*)&a | ((uint32_t)*(uint16_t*)&b << 16);
}
__device__ __forceinline__ void split2(float a, float b, uint32_t& hw, uint32_t& lw) {
    __nv_bfloat16 ha = __float2bfloat16(a), hb = __float2bfloat16(b);
    hw = packbf(ha, hb);
    lw = packbf(__float2bfloat16(a - __bfloat162float(ha)),
                __float2bfloat16(b - __bfloat162float(hb)));
}
__device__ __forceinline__ float fast_exp(float x) {
    float y = fmaxf(x * 1.4426950408889634f, -100.0f);
    float z = y + 12582912.0f;
    int   n = __float_as_int(z) - 0x4B400000;
    float f = y - (z - 12582912.0f);
    float p = 1.33335581e-3f;
    p = fmaf(p, f, 9.61812911e-3f);
    p = fmaf(p, f, 5.55041087e-2f);
    p = fmaf(p, f, 2.40226507e-1f);
    p = fmaf(p, f, 6.93147181e-1f);
    p = fmaf(p, f, 1.0f);
    return __int_as_float(__float_as_int(p) + (n << 23));
}
__device__ __forceinline__ void ldsm_x4(uint32_t a, uint32_t& r0, uint32_t& r1,
                                        uint32_t& r2, uint32_t& r3) {
    asm volatile("ldmatrix.sync.aligned.m8n8.x4.shared.b16 {%0,%1,%2,%3}, [%4];"
        : "=r"(r0), "=r"(r1), "=r"(r2), "=r"(r3) : "r"(a));
}
__device__ __forceinline__ void ldsm_x4t(uint32_t a, uint32_t& r0, uint32_t& r1,
                                         uint32_t& r2, uint32_t& r3) {
    asm volatile("ldmatrix.sync.aligned.m8n8.x4.trans.shared.b16 {%0,%1,%2,%3}, [%4];"
        : "=r"(r0), "=r"(r1), "=r"(r2), "=r"(r3) : "r"(a));
}
__device__ __forceinline__ void mma16816(float* c, const uint32_t* a,
                                         uint32_t b0, uint32_t b1) {
    asm volatile("mma.sync.aligned.m16n8k16.row.col.f32.bf16.bf16.f32 "
        "{%0,%1,%2,%3}, {%4,%5,%6,%7}, {%8,%9}, {%0,%1,%2,%3};"
        : "+f"(c[0]), "+f"(c[1]), "+f"(c[2]), "+f"(c[3])
        : "r"(a[0]), "r"(a[1]), "r"(a[2]), "r"(a[3]), "r"(b0), "r"(b1));
}
__device__ __forceinline__ void cpa16(uint32_t dst, const void* src) {
    asm volatile("cp.async.cg.shared.global [%0], [%1], 16;" :: "r"(dst), "l"(src));
}
__device__ __forceinline__ void cpcommit() { asm volatile("cp.async.commit_group;"); }
__device__ __forceinline__ void cpwait1()  { asm volatile("cp.async.wait_group 1;"); }
__device__ __forceinline__ void cpwait0()  { asm volatile("cp.async.wait_group 0;"); }

// ---------------- prep: split X ----------------
__global__ __launch_bounds__(256) void prep_x(const float* __restrict__ X) {
    size_t i = (size_t)blockIdx.x * 256 + threadIdx.x;
    float4 v = ((const float4*)X)[i];
    uint32_t h0, l0, h1, l1;
    split2(v.x, v.y, h0, l0);
    split2(v.z, v.w, h1, l1);
    ((uint2*)g_Xh)[i] = make_uint2(h0, h1);
    ((uint2*)g_Xl)[i] = make_uint2(l0, l1);
}

// ---------------- prep: transpose+split W -> [mat][h*64+e][d] ----------------
__global__ __launch_bounds__(256) void prep_w(const float* __restrict__ Wq,
                                              const float* __restrict__ Wk,
                                              const float* __restrict__ Wv) {
    int z = blockIdx.z, mat = z >> 4, h = z & 15;
    const float* W = (mat == 0 ? Wq : (mat == 1 ? Wk : Wv)) + (size_t)h * 1024 * 64;
    __shared__ float t[32][33];
    int d0 = blockIdx.x * 32, e0 = blockIdx.y * 32;
    int tx = threadIdx.x, ty = threadIdx.y;
    #pragma unroll
    for (int k = 0; k < 4; k++)
        t[ty + 8 * k][tx] = W[(size_t)(d0 + ty + 8 * k) * 64 + e0 + tx];
    __syncthreads();
    __nv_bfloat16* oh = g_Wh + (size_t)mat * 1048576;
    __nv_bfloat16* ol = g_Wl + (size_t)mat * 1048576;
    #pragma unroll
    for (int k = 0; k < 4; k++) {
        int j = ty + 8 * k;
        float v = t[tx][j];
        __nv_bfloat16 hv = __float2bfloat16(v);
        size_t o = (size_t)(h * 64 + e0 + j) * 1024 + d0 + tx;
        oh[o] = hv;
        ol[o] = __float2bfloat16(v - __bfloat162float(hv));
    }
}

// ---------------- QKV GEMM: 128x64 CTA tile, cp.async double buffer ----------------
#define GP 40
#define QKV_SMEM (2 * 15360 * 2)

__device__ __forceinline__ void qkv_prefetch(uint32_t sb, int st, int stile, int octile,
                                             int kc, int tid,
                                             const __nv_bfloat16* Bh,
                                             const __nv_bfloat16* Bl) {
    uint32_t s0 = sb + st * 15360 * 2;
    #pragma unroll
    for (int i = tid; i < 512; i += 256) {
        int r = i >> 2, c8 = i & 3;
        uint32_t d = s0 + (r * GP + c8 * 8) * 2;
        size_t g = (size_t)(stile * 128 + r) * 1024 + kc * 32 + c8 * 8;
        cpa16(d, g_Xh + g);
        cpa16(d + 5120 * 2, g_Xl + g);
    }
    {
        int i = tid;
        int r = i >> 2, c8 = i & 3;
        uint32_t d = s0 + (10240 + r * GP + c8 * 8) * 2;
        size_t g = (size_t)(octile * 64 + r) * 1024 + kc * 32 + c8 * 8;
        cpa16(d, Bh + g);
        cpa16(d + 2560 * 2, Bl + g);
    }
}

__global__ __launch_bounds__(256, 2) void qkv_mm(const float* __restrict__ bq,
                                                 const float* __restrict__ bk,
                                                 const float* __restrict__ bv) {
    extern __shared__ __align__(16) __nv_bfloat16 smq[];
    uint32_t sb = smem_u32(smq);
    int tid = threadIdx.x, lane = tid & 31, wid = tid >> 5;
    int stile = blockIdx.x, octile = blockIdx.y, mat = blockIdx.z;
    int wm = wid >> 1, wn = wid & 1;
    int lm = lane & 15;

    const __nv_bfloat16* Bh = g_Wh + (size_t)mat * 1048576;
    const __nv_bfloat16* Bl = g_Wl + (size_t)mat * 1048576;

    float C[2][4][4] = {};

    qkv_prefetch(sb, 0, stile, octile, 0, tid, Bh, Bl);
    cpcommit();

    for (int kc = 0; kc < 32; kc++) {
        if (kc < 31) {
            qkv_prefetch(sb, (kc + 1) & 1, stile, octile, kc + 1, tid, Bh, Bl);
            cpcommit();
            cpwait1();
        } else {
            cpwait0();
        }
        __syncthreads();
        uint32_t bufA = sb + (kc & 1) * 15360 * 2;
        uint32_t bufBh = bufA + 10240 * 2, bufBl = bufA + 12800 * 2;
        #pragma unroll
        for (int ks = 0; ks < 2; ks++) {
            uint32_t ah[2][4], al[2][4];
            #pragma unroll
            for (int mt = 0; mt < 2; mt++) {
                uint32_t off = ((uint32_t)(wm * 32 + mt * 16 + lm) * GP
                                + ks * 16 + ((lane >> 4) << 3)) * 2;
                ldsm_x4(bufA + off, ah[mt][0], ah[mt][1], ah[mt][2], ah[mt][3]);
                ldsm_x4(bufA + 5120 * 2 + off, al[mt][0], al[mt][1], al[mt][2], al[mt][3]);
            }
            #pragma unroll
            for (int ntp = 0; ntp < 2; ntp++) {
                uint32_t off = ((uint32_t)(wn * 32 + ntp * 16 + ((lane >> 4) << 3) + (lane & 7)) * GP
                                + ks * 16 + (((lane >> 3) & 1) << 3)) * 2;
                uint32_t h0, h1, h2, h3, l0, l1, l2, l3;
                ldsm_x4(bufBh + off, h0, h1, h2, h3);
                ldsm_x4(bufBl + off, l0, l1, l2, l3);
                #pragma unroll
                for (int mt = 0; mt < 2; mt++) {
                    mma16816(C[mt][2 * ntp],     ah[mt], h0, h1);
                    mma16816(C[mt][2 * ntp],     ah[mt], l0, l1);
                    mma16816(C[mt][2 * ntp],     al[mt], h0, h1);
                    mma16816(C[mt][2 * ntp + 1], ah[mt], h2, h3);
                    mma16816(C[mt][2 * ntp + 1], ah[mt], l2, l3);
                    mma16816(C[mt][2 * ntp + 1], al[mt], h2, h3);
                }
            }
        }
        __syncthreads();
    }

    const float* bias = (mat == 0 ? bq : (mat == 1 ? bk : bv));
    float scale = (mat == 0) ? 0.125f : 1.0f;
    __nv_bfloat16* Dh = (mat == 0 ? g_Qh : (mat == 1 ? g_Kh : g_Vh));
    __nv_bfloat16* Dl = (mat == 0 ? g_Ql : (mat == 1 ? g_Kl : g_Vl));
    #pragma unroll
    for (int mt = 0; mt < 2; mt++) {
        #pragma unroll
        for (int nt = 0; nt < 4; nt++) {
            int col = octile * 64 + wn * 32 + nt * 8 + 2 * (lane & 3);
            float b0 = __ldg(bias + col), b1 = __ldg(bias + col + 1);
            int hh = col >> 6, e = col & 63;
            #pragma unroll
            for (int hf = 0; hf < 2; hf++) {
                int row = stile * 128 + wm * 32 + mt * 16 + (lane >> 2) + 8 * hf;
                float v0 = (C[mt][nt][2 * hf + 0] + b0) * scale;
                float v1 = (C[mt][nt][2 * hf + 1] + b1) * scale;
                uint32_t hw, lw;
                split2(v0, v1, hw, lw);
                int b = row >> 11, s = row & 2047;
                size_t o = ((size_t)(b * 16 + hh) * 2048 + s) * 64 + e;
                *(uint32_t*)&Dh[o] = hw;
                *(uint32_t*)&Dl[o] = lw;
            }
        }
    }
}

// ---------------- attention: 128 thr / 4 warps x 32 q-rows, 2 CTAs/SM ----------------
#define REG 8192                       // region: 64 rows x 64 bf16 = 8KB
#define STAGE (4 * REG)                // KH KL VH VL = 32KB
#define A_SMEM (2 * STAGE)             // 64KB

__device__ __forceinline__ uint32_t swoff(int r, int c8) {
    return (uint32_t)(((r << 3) + (c8 ^ (r & 7))) << 4);
}

// prefetch one 64-row kv tile; masked tiles need only K-hi
__device__ __forceinline__ void attn_prefetch(uint32_t s0, int tid,
                                              const __nv_bfloat16* Kh,
                                              const __nv_bfloat16* Kl,
                                              const __nv_bfloat16* Vh,
                                              const __nv_bfloat16* Vl, bool full) {
    #pragma unroll
    for (int i = tid; i < 512; i += 128) {
        int r = i >> 3, c8 = i & 7;
        uint32_t d = swoff(r, c8);
        size_t g = (size_t)r * 64 + c8 * 8;
        cpa16(s0 + d, Kh + g);
        if (full) {
            cpa16(s0 + REG + d,     Kl + g);
            cpa16(s0 + 2 * REG + d, Vh + g);
            cpa16(s0 + 3 * REG + d, Vl + g);
        }
    }
}

// S slice (32 rows x 16 cols): 3-term live, 1-term masked (denominator only)
__device__ __forceinline__ void compS32(uint32_t sK, uint32_t sKl, int k2, int lane,
                                        const uint32_t qh[2][4][4],
                                        const uint32_t ql[2][4][4],
                                        bool full, float S[2][2][4]) {
    #pragma unroll
    for (int mt = 0; mt < 2; mt++)
        #pragma unroll
        for (int z = 0; z < 4; z++) { S[mt][0][z] = 0.f; S[mt][1][z] = 0.f; }
    #pragma unroll
    for (int ks = 0; ks < 4; ks++) {
        int row = k2 * 16 + ((lane >> 4) << 3) + (lane & 7);
        int c8 = ks * 2 + ((lane >> 3) & 1);
        uint32_t d = swoff(row, c8);
        uint32_t h0, h1, h2, h3;
        ldsm_x4(sK + d, h0, h1, h2, h3);
        if (full) {
            uint32_t l0, l1, l2, l3;
            ldsm_x4(sKl + d, l0, l1, l2, l3);
            #pragma unroll
            for (int mt = 0; mt < 2; mt++) {
                mma16816(S[mt][0], qh[mt][ks], h0, h1);
                mma16816(S[mt][0], qh[mt][ks], l0, l1);
                mma16816(S[mt][0], ql[mt][ks], h0, h1);
                mma16816(S[mt][1], qh[mt][ks], h2, h3);
                mma16816(S[mt][1], qh[mt][ks], l2, l3);
                mma16816(S[mt][1], ql[mt][ks], h2, h3);
            }
        } else {
            #pragma unroll
            for (int mt = 0; mt < 2; mt++) {
                mma16816(S[mt][0], qh[mt][ks], h0, h1);
                mma16816(S[mt][1], qh[mt][ks], h2, h3);
            }
        }
    }
}

__global__ __launch_bounds__(128, 2) void attn(float* __restrict__ out) {
    extern __shared__ __align__(16) char sm[];
    uint32_t sb = smem_u32(sm);
    int tid = threadIdx.x, lane = tid & 31, w = tid >> 5;   // w: 0..3
    int bh = blockIdx.x >> 4, qt = 15 - (blockIdx.x & 15);  // heavy-first
    int b = bh >> 4, h = bh & 15;
    int lm = lane & 15;

    // ---- stage Q (128x64 h/l) through stage-0 buffer, extract fragments, recycle
    const __nv_bfloat16* Qh = g_Qh + ((size_t)bh * 2048 + qt * 128) * 64;
    const __nv_bfloat16* Ql = g_Ql + ((size_t)bh * 2048 + qt * 128) * 64;
    #pragma unroll
    for (int i = tid; i < 1024; i += 128) {
        int r = i >> 3, c8 = i & 7;
        uint32_t d = ((r >= 64) ? REG : 0) + swoff(r & 63, c8);
        size_t g = (size_t)r * 64 + c8 * 8;
        cpa16(sb + d,           Qh + g);
        cpa16(sb + 2 * REG + d, Ql + g);
    }
    cpcommit(); cpwait0();
    __syncthreads();

    uint32_t qh[2][4][4], ql[2][4][4];
    #pragma unroll
    for (int mt = 0; mt < 2; mt++) {
        int r = w * 32 + mt * 16 + lm;
        uint32_t qreg = (r >= 64) ? REG : 0;
        int rr = r & 63;
        #pragma unroll
        for (int ks = 0; ks < 4; ks++) {
            int c8 = ks * 2 + (lane >> 4);
            uint32_t d = swoff(rr, c8);
            ldsm_x4(sb + qreg + d,           qh[mt][ks][0], qh[mt][ks][1], qh[mt][ks][2], qh[mt][ks][3]);
            ldsm_x4(sb + qreg + 2 * REG + d, ql[mt][ks][0], ql[mt][ks][1], ql[mt][ks][2], ql[mt][ks][3]);
        }
    }
    __syncthreads();   // Q smem free -> pipeline may overwrite

    const __nv_bfloat16* Khb = g_Kh + (size_t)bh * 2048 * 64;
    const __nv_bfloat16* Klb = g_Kl + (size_t)bh * 2048 * 64;
    const __nv_bfloat16* Vhb = g_Vh + (size_t)bh * 2048 * 64;
    const __nv_bfloat16* Vlb = g_Vl + (size_t)bh * 2048 * 64;

    int kmax = 2 * qt + 1;
    attn_prefetch(sb, tid, Khb, Klb, Vhb, Vlb, true);
    cpcommit();

    float O[2][8][4] = {};
    float lsum[2][2] = {};

    for (int kt = 0; kt < 32; kt++) {
        if (kt < 31) {
            size_t off = (size_t)(kt + 1) * 64 * 64;
            attn_prefetch(sb + ((kt + 1) & 1) * STAGE, tid,
                          Khb + off, Klb + off, Vhb + off, Vlb + off, (kt + 1) <= kmax);
            cpcommit();
            cpwait1();
        } else {
            cpwait0();
        }
        __syncthreads();

        uint32_t sK = sb + (kt & 1) * STAGE;
        uint32_t sKl = sK + REG, sV = sK + 2 * REG, sVl = sK + 3 * REG;
        bool live = (kt <= kmax);
        int cb = kt * 64 + 2 * (lane & 3);

        float Sc[2][2][4];
        compS32(sK, sKl, 0, lane, qh, ql, live, Sc);

        #pragma unroll
        for (int k2 = 0; k2 < 4; k2++) {
            float Sn[2][2][4];
            if (k2 < 3) compS32(sK, sKl, k2 + 1, lane, qh, ql, live, Sn);

            // ---- exp + full-row lsum + post-softmax tril mask
            #pragma unroll
            for (int mt = 0; mt < 2; mt++) {
                int rb = qt * 128 + w * 32 + mt * 16 + (lane >> 2);
                #pragma unroll
                for (int ntl = 0; ntl < 2; ntl++) {
                    int colg = cb + k2 * 16 + ntl * 8;
                    #pragma unroll
                    for (int hf = 0; hf < 2; hf++) {
                        int rg = rb + 8 * hf;
                        float e0 = fast_exp(Sc[mt][ntl][2 * hf + 0]);
                        float e1 = fast_exp(Sc[mt][ntl][2 * hf + 1]);
                        lsum[mt][hf] += e0 + e1;
                        Sc[mt][ntl][2 * hf + 0] = (colg     <= rg) ? e0 : 0.f;
                        Sc[mt][ntl][2 * hf + 1] = (colg + 1 <= rg) ? e1 : 0.f;
                    }
                }
            }
            // ---- PV for this 16-wide k-slice
            if (live) {
                uint32_t pah[2][4], pal[2][4];
                #pragma unroll
                for (int mt = 0; mt < 2; mt++) {
                    split2(Sc[mt][0][0], Sc[mt][0][1], pah[mt][0], pal[mt][0]);
                    split2(Sc[mt][0][2], Sc[mt][0][3], pah[mt][1], pal[mt][1]);
                    split2(Sc[mt][1][0], Sc[mt][1][1], pah[mt][2], pal[mt][2]);
                    split2(Sc[mt][1][2], Sc[mt][1][3], pah[mt][3], pal[mt][3]);
                }
                #pragma unroll
                for (int ntp = 0; ntp < 4; ntp++) {
                    int row = k2 * 16 + lm;
                    int c8 = ntp * 2 + (lane >> 4);
                    uint32_t d = swoff(row, c8);
                    uint32_t v0, v1, v2, v3, u0, u1, u2, u3;
                    ldsm_x4t(sV + d,  v0, v1, v2, v3);
                    ldsm_x4t(sVl + d, u0, u1, u2, u3);
                    #pragma unroll
                    for (int mt = 0; mt < 2; mt++) {
                        mma16816(O[mt][2 * ntp],     pah[mt], v0, v1);
                        mma16816(O[mt][2 * ntp],     pah[mt], u0, u1);
                        mma16816(O[mt][2 * ntp],     pal[mt], v0, v1);
                        mma16816(O[mt][2 * ntp + 1], pah[mt], v2, v3);
                        mma16816(O[mt][2 * ntp + 1], pah[mt], u2, u3);
                        mma16816(O[mt][2 * ntp + 1], pal[mt], v2, v3);
                    }
                }
            }
            if (k2 < 3) {
                #pragma unroll
                for (int mt = 0; mt < 2; mt++)
                    #pragma unroll
                    for (int ntl = 0; ntl < 2; ntl++)
                        #pragma unroll
                        for (int z = 0; z < 4; z++) Sc[mt][ntl][z] = Sn[mt][ntl][z];
            }
        }
        __syncthreads();
    }

    // ---- row denominators: quad butterfly (warp-local rows)
    #pragma unroll
    for (int mt = 0; mt < 2; mt++)
        #pragma unroll
        for (int hf = 0; hf < 2; hf++) {
            lsum[mt][hf] += __shfl_xor_sync(0xffffffffu, lsum[mt][hf], 1);
            lsum[mt][hf] += __shfl_xor_sync(0xffffffffu, lsum[mt][hf], 2);
        }

    // ---- write out
    #pragma unroll
    for (int mt = 0; mt < 2; mt++)
        #pragma unroll
        for (int hf = 0; hf < 2; hf++) {
            float inv = 1.0f / lsum[mt][hf];
            int rg = qt * 128 + w * 32 + mt * 16 + (lane >> 2) + 8 * hf;
            float* ob = out + ((size_t)b * 2048 + rg) * 1024 + h * 64;
            #pragma unroll
            for (int nt = 0; nt < 8; nt++) {
                int c = nt * 8 + 2 * (lane & 3);
                *(float2*)&ob[c] = make_float2(O[mt][nt][2 * hf] * inv,
                                               O[mt][nt][2 * hf + 1] * inv);
            }
        }
}

extern "C" void kernel_launch(void* const* d_in, const int* in_sizes, int n_in,
                              void* d_out, int out_size) {
    const float* X  = (const float*)d_in[0];
    const float* Wq = (const float*)d_in[1];
    const float* bq = (const float*)d_in[2];
    const float* Wk = (const float*)d_in[3];
    const float* bk = (const float*)d_in[4];
    const float* Wv = (const float*)d_in[5];
    const float* bv = (const float*)d_in[6];

    cudaFuncSetAttribute(qkv_mm, cudaFuncAttributeMaxDynamicSharedMemorySize, QKV_SMEM);
    cudaFuncSetAttribute(attn,   cudaFuncAttributeMaxDynamicSharedMemorySize, A_SMEM);

    prep_x<<<4096, 256>>>(X);
    prep_w<<<dim3(32, 2, 48), dim3(32, 8)>>>(Wq, Wk, Wv);
    qkv_mm<<<dim3(32, 16, 3), 256, QKV_SMEM>>>(bq, bk, bv);
    attn<<<512, 128, A_SMEM>>>((float*)d_out);
}

// round 9
// speedup vs baseline: 1.0115x; 1.0115x over previous
#include <cuda_runtime.h>
#include <cuda_bf16.h>
#include <cstdint>

// ---------------- scratch (device globals) ----------------
__device__ __align__(16) __nv_bfloat16 g_Xh[4096*1024], g_Xl[4096*1024];
__device__ __align__(16) __nv_bfloat16 g_Wh[3*1024*1024], g_Wl[3*1024*1024];
__device__ __align__(16) __nv_bfloat16 g_Qh[32*2048*64], g_Ql[32*2048*64];
__device__ __align__(16) __nv_bfloat16 g_Kh[32*2048*64], g_Kl[32*2048*64];
__device__ __align__(16) __nv_bfloat16 g_Vh[32*2048*64], g_Vl[32*2048*64];

// ---------------- helpers ----------------
__device__ __forceinline__ uint32_t smem_u32(const void* p) {
    uint32_t a;
    asm("{ .reg .u64 t; cvta.to.shared.u64 t, %1; cvt.u32.u64 %0, t; }" : "=r"(a) : "l"(p));
    return a;
}
// truncation-based hi/lo split: hi = bf16_trunc(x), lo = bf16_trunc(x - hi).
// pure shift/mask + 1 FSUB per value (no cvt.rn chains). |err| ~ 2^-17 vs 2^-18 RN.
__device__ __forceinline__ void split2(float a, float b, uint32_t& hw, uint32_t& lw) {
    uint32_t ua = __float_as_uint(a), ub = __float_as_uint(b);
    hw = (ua >> 16) | (ub & 0xFFFF0000u);
    float la = a - __uint_as_float(ua & 0xFFFF0000u);
    float lb = b - __uint_as_float(ub & 0xFFFF0000u);
    lw = (__float_as_uint(la) >> 16) | (__float_as_uint(lb) & 0xFFFF0000u);
}
__device__ __forceinline__ float fast_exp(float x) {
    float y = fmaxf(x * 1.4426950408889634f, -100.0f);
    float z = y + 12582912.0f;
    int   n = __float_as_int(z) - 0x4B400000;
    float f = y - (z - 12582912.0f);
    float p = 1.33335581e-3f;
    p = fmaf(p, f, 9.61812911e-3f);
    p = fmaf(p, f, 5.55041087e-2f);
    p = fmaf(p, f, 2.40226507e-1f);
    p = fmaf(p, f, 6.93147181e-1f);
    p = fmaf(p, f, 1.0f);
    return __int_as_float(__float_as_int(p) + (n << 23));
}
__device__ __forceinline__ void ldsm_x4(uint32_t a, uint32_t& r0, uint32_t& r1,
                                        uint32_t& r2, uint32_t& r3) {
    asm volatile("ldmatrix.sync.aligned.m8n8.x4.shared.b16 {%0,%1,%2,%3}, [%4];"
        : "=r"(r0), "=r"(r1), "=r"(r2), "=r"(r3) : "r"(a));
}
__device__ __forceinline__ void ldsm_x4t(uint32_t a, uint32_t& r0, uint32_t& r1,
                                         uint32_t& r2, uint32_t& r3) {
    asm volatile("ldmatrix.sync.aligned.m8n8.x4.trans.shared.b16 {%0,%1,%2,%3}, [%4];"
        : "=r"(r0), "=r"(r1), "=r"(r2), "=r"(r3) : "r"(a));
}
// NOTE: not volatile — register-only op; lets the compiler interleave MMA chains
// and schedule them across (volatile) ldsm boundaries. Data deps keep correctness.
__device__ __forceinline__ void mma16816(float* c, const uint32_t* a,
                                         uint32_t b0, uint32_t b1) {
    asm("mma.sync.aligned.m16n8k16.row.col.f32.bf16.bf16.f32 "
        "{%0,%1,%2,%3}, {%4,%5,%6,%7}, {%8,%9}, {%0,%1,%2,%3};"
        : "+f"(c[0]), "+f"(c[1]), "+f"(c[2]), "+f"(c[3])
        : "r"(a[0]), "r"(a[1]), "r"(a[2]), "r"(a[3]), "r"(b0), "r"(b1));
}
__device__ __forceinline__ void cpa16(uint32_t dst, const void* src) {
    asm volatile("cp.async.cg.shared.global [%0], [%1], 16;" :: "r"(dst), "l"(src));
}
__device__ __forceinline__ void cpcommit() { asm volatile("cp.async.commit_group;"); }
__device__ __forceinline__ void cpwait1()  { asm volatile("cp.async.wait_group 1;"); }
__device__ __forceinline__ void cpwait0()  { asm volatile("cp.async.wait_group 0;"); }

// ---------------- prep: split X ----------------
__global__ __launch_bounds__(256) void prep_x(const float* __restrict__ X) {
    size_t i = (size_t)blockIdx.x * 256 + threadIdx.x;
    float4 v = ((const float4*)X)[i];
    uint32_t h0, l0, h1, l1;
    split2(v.x, v.y, h0, l0);
    split2(v.z, v.w, h1, l1);
    ((uint2*)g_Xh)[i] = make_uint2(h0, h1);
    ((uint2*)g_Xl)[i] = make_uint2(l0, l1);
}

// ---------------- prep: transpose+split W -> [mat][h*64+e][d] ----------------
__global__ __launch_bounds__(256) void prep_w(const float* __restrict__ Wq,
                                              const float* __restrict__ Wk,
                                              const float* __restrict__ Wv) {
    int z = blockIdx.z, mat = z >> 4, h = z & 15;
    const float* W = (mat == 0 ? Wq : (mat == 1 ? Wk : Wv)) + (size_t)h * 1024 * 64;
    __shared__ float t[32][33];
    int d0 = blockIdx.x * 32, e0 = blockIdx.y * 32;
    int tx = threadIdx.x, ty = threadIdx.y;
    #pragma unroll
    for (int k = 0; k < 4; k++)
        t[ty + 8 * k][tx] = W[(size_t)(d0 + ty + 8 * k) * 64 + e0 + tx];
    __syncthreads();
    __nv_bfloat16* oh = g_Wh + (size_t)mat * 1048576;
    __nv_bfloat16* ol = g_Wl + (size_t)mat * 1048576;
    #pragma unroll
    for (int k = 0; k < 4; k++) {
        int j = ty + 8 * k;
        float v = t[tx][j];
        uint32_t uv = __float_as_uint(v);
        float hv = __uint_as_float(uv & 0xFFFF0000u);
        size_t o = (size_t)(h * 64 + e0 + j) * 1024 + d0 + tx;
        *(uint16_t*)&oh[o] = (uint16_t)(uv >> 16);
        *(uint16_t*)&ol[o] = (uint16_t)(__float_as_uint(v - hv) >> 16);
    }
}

// ---------------- QKV GEMM: 128x64 CTA tile, cp.async double buffer ----------------
#define GP 40
#define QKV_SMEM (2 * 15360 * 2)

__device__ __forceinline__ void qkv_prefetch(uint32_t sb, int st, int stile, int octile,
                                             int kc, int tid,
                                             const __nv_bfloat16* Bh,
                                             const __nv_bfloat16* Bl) {
    uint32_t s0 = sb + st * 15360 * 2;
    #pragma unroll
    for (int i = tid; i < 512; i += 256) {
        int r = i >> 2, c8 = i & 3;
        uint32_t d = s0 + (r * GP + c8 * 8) * 2;
        size_t g = (size_t)(stile * 128 + r) * 1024 + kc * 32 + c8 * 8;
        cpa16(d, g_Xh + g);
        cpa16(d + 5120 * 2, g_Xl + g);
    }
    {
        int i = tid;
        int r = i >> 2, c8 = i & 3;
        uint32_t d = s0 + (10240 + r * GP + c8 * 8) * 2;
        size_t g = (size_t)(octile * 64 + r) * 1024 + kc * 32 + c8 * 8;
        cpa16(d, Bh + g);
        cpa16(d + 2560 * 2, Bl + g);
    }
}

__global__ __launch_bounds__(256, 2) void qkv_mm(const float* __restrict__ bq,
                                                 const float* __restrict__ bk,
                                                 const float* __restrict__ bv) {
    extern __shared__ __align__(16) __nv_bfloat16 smq[];
    uint32_t sb = smem_u32(smq);
    int tid = threadIdx.x, lane = tid & 31, wid = tid >> 5;
    int stile = blockIdx.x, octile = blockIdx.y, mat = blockIdx.z;
    int wm = wid >> 1, wn = wid & 1;
    int lm = lane & 15;

    const __nv_bfloat16* Bh = g_Wh + (size_t)mat * 1048576;
    const __nv_bfloat16* Bl = g_Wl + (size_t)mat * 1048576;

    float C[2][4][4] = {};

    qkv_prefetch(sb, 0, stile, octile, 0, tid, Bh, Bl);
    cpcommit();

    for (int kc = 0; kc < 32; kc++) {
        if (kc < 31) {
            qkv_prefetch(sb, (kc + 1) & 1, stile, octile, kc + 1, tid, Bh, Bl);
            cpcommit();
            cpwait1();
        } else {
            cpwait0();
        }
        __syncthreads();
        uint32_t bufA = sb + (kc & 1) * 15360 * 2;
        uint32_t bufBh = bufA + 10240 * 2, bufBl = bufA + 12800 * 2;
        #pragma unroll
        for (int ks = 0; ks < 2; ks++) {
            uint32_t ah[2][4], al[2][4];
            #pragma unroll
            for (int mt = 0; mt < 2; mt++) {
                uint32_t off = ((uint32_t)(wm * 32 + mt * 16 + lm) * GP
                                + ks * 16 + ((lane >> 4) << 3)) * 2;
                ldsm_x4(bufA + off, ah[mt][0], ah[mt][1], ah[mt][2], ah[mt][3]);
                ldsm_x4(bufA + 5120 * 2 + off, al[mt][0], al[mt][1], al[mt][2], al[mt][3]);
            }
            #pragma unroll
            for (int ntp = 0; ntp < 2; ntp++) {
                uint32_t off = ((uint32_t)(wn * 32 + ntp * 16 + ((lane >> 4) << 3) + (lane & 7)) * GP
                                + ks * 16 + (((lane >> 3) & 1) << 3)) * 2;
                uint32_t h0, h1, h2, h3, l0, l1, l2, l3;
                ldsm_x4(bufBh + off, h0, h1, h2, h3);
                ldsm_x4(bufBl + off, l0, l1, l2, l3);
                #pragma unroll
                for (int mt = 0; mt < 2; mt++) {
                    mma16816(C[mt][2 * ntp],     ah[mt], h0, h1);
                    mma16816(C[mt][2 * ntp],     ah[mt], l0, l1);
                    mma16816(C[mt][2 * ntp],     al[mt], h0, h1);
                    mma16816(C[mt][2 * ntp + 1], ah[mt], h2, h3);
                    mma16816(C[mt][2 * ntp + 1], ah[mt], l2, l3);
                    mma16816(C[mt][2 * ntp + 1], al[mt], h2, h3);
                }
            }
        }
        __syncthreads();
    }

    const float* bias = (mat == 0 ? bq : (mat == 1 ? bk : bv));
    float scale = (mat == 0) ? 0.125f : 1.0f;
    __nv_bfloat16* Dh = (mat == 0 ? g_Qh : (mat == 1 ? g_Kh : g_Vh));
    __nv_bfloat16* Dl = (mat == 0 ? g_Ql : (mat == 1 ? g_Kl : g_Vl));
    #pragma unroll
    for (int mt = 0; mt < 2; mt++) {
        #pragma unroll
        for (int nt = 0; nt < 4; nt++) {
            int col = octile * 64 + wn * 32 + nt * 8 + 2 * (lane & 3);
            float b0 = __ldg(bias + col), b1 = __ldg(bias + col + 1);
            int hh = col >> 6, e = col & 63;
            #pragma unroll
            for (int hf = 0; hf < 2; hf++) {
                int row = stile * 128 + wm * 32 + mt * 16 + (lane >> 2) + 8 * hf;
                float v0 = (C[mt][nt][2 * hf + 0] + b0) * scale;
                float v1 = (C[mt][nt][2 * hf + 1] + b1) * scale;
                uint32_t hw, lw;
                split2(v0, v1, hw, lw);
                int b = row >> 11, s = row & 2047;
                size_t o = ((size_t)(b * 16 + hh) * 2048 + s) * 64 + e;
                *(uint32_t*)&Dh[o] = hw;
                *(uint32_t*)&Dl[o] = lw;
            }
        }
    }
}

// ---------------- attention: 256 thr, 8 warps x 16 q-rows, 2 CTAs/SM ----------------
#define REG 8192                       // region: 64 rows x 64 bf16 = 8KB
#define STAGE (4 * REG)                // KH KL VH VL = 32KB
#define A_SMEM (2 * STAGE)             // 64KB

__device__ __forceinline__ uint32_t swoff(int r, int c8) {
    return (uint32_t)(((r << 3) + (c8 ^ (r & 7))) << 4);
}

// prefetch one 64-row kv tile; masked tiles need only K-hi
__device__ __forceinline__ void attn_prefetch(uint32_t s0, int tid,
                                              const __nv_bfloat16* Kh,
                                              const __nv_bfloat16* Kl,
                                              const __nv_bfloat16* Vh,
                                              const __nv_bfloat16* Vl, bool full) {
    #pragma unroll
    for (int i = tid; i < 512; i += 256) {
        int r = i >> 3, c8 = i & 7;
        uint32_t d = swoff(r, c8);
        size_t g = (size_t)r * 64 + c8 * 8;
        cpa16(s0 + d, Kh + g);
        if (full) {
            cpa16(s0 + REG + d,     Kl + g);
            cpa16(s0 + 2 * REG + d, Vh + g);
            cpa16(s0 + 3 * REG + d, Vl + g);
        }
    }
}

// S slice (16 rows x 16 cols): 3-term live; 1-term (qh·kh) masked (denominator only)
__device__ __forceinline__ void compS(uint32_t sK, uint32_t sKl, int k2, int lane,
                                      const uint32_t qh[4][4], const uint32_t ql[4][4],
                                      bool full, float S[2][4]) {
    #pragma unroll
    for (int z = 0; z < 4; z++) { S[0][z] = 0.f; S[1][z] = 0.f; }
    #pragma unroll
    for (int ks = 0; ks < 4; ks++) {
        int row = k2 * 16 + ((lane >> 4) << 3) + (lane & 7);
        int c8 = ks * 2 + ((lane >> 3) & 1);
        uint32_t d = swoff(row, c8);
        uint32_t h0, h1, h2, h3;
        ldsm_x4(sK + d, h0, h1, h2, h3);
        if (full) {
            uint32_t l0, l1, l2, l3;
            ldsm_x4(sKl + d, l0, l1, l2, l3);
            mma16816(S[0], qh[ks], h0, h1);
            mma16816(S[0], qh[ks], l0, l1);
            mma16816(S[0], ql[ks], h0, h1);
            mma16816(S[1], qh[ks], h2, h3);
            mma16816(S[1], qh[ks], l2, l3);
            mma16816(S[1], ql[ks], h2, h3);
        } else {
            mma16816(S[0], qh[ks], h0, h1);
            mma16816(S[1], qh[ks], h2, h3);
        }
    }
}

__global__ __launch_bounds__(256, 2) void attn(float* __restrict__ out) {
    extern __shared__ __align__(16) char sm[];
    uint32_t sb = smem_u32(sm);
    int tid = threadIdx.x, lane = tid & 31, w = tid >> 5;
    int bh = blockIdx.x >> 4, qt = 15 - (blockIdx.x & 15);  // heavy-first
    int b = bh >> 4, h = bh & 15;
    int lm = lane & 15;

    // ---- stage Q (128x64 h/l) through stage-0 buffer, extract fragments, recycle
    const __nv_bfloat16* Qh = g_Qh + ((size_t)bh * 2048 + qt * 128) * 64;
    const __nv_bfloat16* Ql = g_Ql + ((size_t)bh * 2048 + qt * 128) * 64;
    #pragma unroll
    for (int i = tid; i < 1024; i += 256) {
        int r = i >> 3, c8 = i & 7;
        uint32_t d = ((r >= 64) ? REG : 0) + swoff(r & 63, c8);
        size_t g = (size_t)r * 64 + c8 * 8;
        cpa16(sb + d,           Qh + g);
        cpa16(sb + 2 * REG + d, Ql + g);
    }
    cpcommit(); cpwait0();
    __syncthreads();

    uint32_t qh[4][4], ql[4][4];
    {
        int r = w * 16 + lm;
        uint32_t qreg = (r >= 64) ? REG : 0;
        int rr = r & 63;
        #pragma unroll
        for (int ks = 0; ks < 4; ks++) {
            int c8 = ks * 2 + (lane >> 4);
            uint32_t d = swoff(rr, c8);
            ldsm_x4(sb + qreg + d,           qh[ks][0], qh[ks][1], qh[ks][2], qh[ks][3]);
            ldsm_x4(sb + qreg + 2 * REG + d, ql[ks][0], ql[ks][1], ql[ks][2], ql[ks][3]);
        }
    }
    __syncthreads();   // Q smem free -> pipeline may overwrite

    const __nv_bfloat16* Khb = g_Kh + (size_t)bh * 2048 * 64;
    const __nv_bfloat16* Klb = g_Kl + (size_t)bh * 2048 * 64;
    const __nv_bfloat16* Vhb = g_Vh + (size_t)bh * 2048 * 64;
    const __nv_bfloat16* Vlb = g_Vl + (size_t)bh * 2048 * 64;

    int kmax = 2 * qt + 1;
    attn_prefetch(sb, tid, Khb, Klb, Vhb, Vlb, true);
    cpcommit();

    float O[8][4] = {};
    float lsum[2] = {};
    int rbase = qt * 128 + w * 16 + (lane >> 2);

    for (int kt = 0; kt < 32; kt++) {
        if (kt < 31) {
            size_t off = (size_t)(kt + 1) * 64 * 64;
            attn_prefetch(sb + ((kt + 1) & 1) * STAGE, tid,
                          Khb + off, Klb + off, Vhb + off, Vlb + off, (kt + 1) <= kmax);
            cpcommit();
            cpwait1();
        } else {
            cpwait0();
        }
        __syncthreads();

        uint32_t sK = sb + (kt & 1) * STAGE;
        uint32_t sKl = sK + REG, sV = sK + 2 * REG, sVl = sK + 3 * REG;
        bool live = (kt <= kmax);
        int cb = kt * 64 + 2 * (lane & 3);

        float Sc[2][4];
        compS(sK, sKl, 0, lane, qh, ql, live, Sc);

        #pragma unroll
        for (int k2 = 0; k2 < 4; k2++) {
            // software pipeline: next slice's S MMAs overlap exp/PV of current
            float Sn[2][4];
            if (k2 < 3) compS(sK, sKl, k2 + 1, lane, qh, ql, live, Sn);

            // ---- exp + full-row lsum + post-softmax tril mask
            #pragma unroll
            for (int ntl = 0; ntl < 2; ntl++) {
                int colg = cb + k2 * 16 + ntl * 8;
                #pragma unroll
                for (int hf = 0; hf < 2; hf++) {
                    int rg = rbase + 8 * hf;
                    float e0 = fast_exp(Sc[ntl][2 * hf + 0]);
                    float e1 = fast_exp(Sc[ntl][2 * hf + 1]);
                    lsum[hf] += e0 + e1;
                    Sc[ntl][2 * hf + 0] = (colg     <= rg) ? e0 : 0.f;
                    Sc[ntl][2 * hf + 1] = (colg + 1 <= rg) ? e1 : 0.f;
                }
            }
            // ---- PV for this 16-wide k-slice (V fragments double-buffered)
            if (live) {
                uint32_t pah[4], pal[4];
                split2(Sc[0][0], Sc[0][1], pah[0], pal[0]);
                split2(Sc[0][2], Sc[0][3], pah[1], pal[1]);
                split2(Sc[1][0], Sc[1][1], pah[2], pal[2]);
                split2(Sc[1][2], Sc[1][3], pah[3], pal[3]);
                int row = k2 * 16 + lm;
                uint32_t vA[8];
                {
                    uint32_t d = swoff(row, (lane >> 4));
                    ldsm_x4t(sV + d,  vA[0], vA[1], vA[2], vA[3]);
                    ldsm_x4t(sVl + d, vA[4], vA[5], vA[6], vA[7]);
                }
                #pragma unroll
                for (int ntp = 0; ntp < 4; ntp++) {
                    uint32_t vB[8];
                    if (ntp < 3) {
                        uint32_t d = swoff(row, (ntp + 1) * 2 + (lane >> 4));
                        ldsm_x4t(sV + d,  vB[0], vB[1], vB[2], vB[3]);
                        ldsm_x4t(sVl + d, vB[4], vB[5], vB[6], vB[7]);
                    }
                    mma16816(O[2 * ntp],     pah, vA[0], vA[1]);
                    mma16816(O[2 * ntp],     pah, vA[4], vA[5]);
                    mma16816(O[2 * ntp],     pal, vA[0], vA[1]);
                    mma16816(O[2 * ntp + 1], pah, vA[2], vA[3]);
                    mma16816(O[2 * ntp + 1], pah, vA[6], vA[7]);
                    mma16816(O[2 * ntp + 1], pal, vA[2], vA[3]);
                    if (ntp < 3) {
                        #pragma unroll
                        for (int z = 0; z < 8; z++) vA[z] = vB[z];
                    }
                }
            }
            if (k2 < 3) {
                #pragma unroll
                for (int ntl = 0; ntl < 2; ntl++)
                    #pragma unroll
                    for (int z = 0; z < 4; z++) Sc[ntl][z] = Sn[ntl][z];
            }
        }
        __syncthreads();   // compute done before next prefetch overwrites other stage
    }

    // ---- row denominators: quad butterfly (warp-local rows)
    #pragma unroll
    for (int hf = 0; hf < 2; hf++) {
        lsum[hf] += __shfl_xor_sync(0xffffffffu, lsum[hf], 1);
        lsum[hf] += __shfl_xor_sync(0xffffffffu, lsum[hf], 2);
    }

    // ---- write out
    #pragma unroll
    for (int hf = 0; hf < 2; hf++) {
        float inv = 1.0f / lsum[hf];
        int rg = rbase + 8 * hf;
        float* ob = out + ((size_t)b * 2048 + rg) * 1024 + h * 64;
        #pragma unroll
        for (int nt = 0; nt < 8; nt++) {
            int c = nt * 8 + 2 * (lane & 3);
            *(float2*)&ob[c] = make_float2(O[nt][2 * hf] * inv, O[nt][2 * hf + 1] * inv);
        }
    }
}

extern "C" void kernel_launch(void* const* d_in, const int* in_sizes, int n_in,
                              void* d_out, int out_size) {
    const float* X  = (const float*)d_in[0];
    const float* Wq = (const float*)d_in[1];
    const float* bq = (const float*)d_in[2];
    const float* Wk = (const float*)d_in[3];
    const float* bk = (const float*)d_in[4];
    const float* Wv = (const float*)d_in[5];
    const float* bv = (const float*)d_in[6];

    cudaFuncSetAttribute(qkv_mm, cudaFuncAttributeMaxDynamicSharedMemorySize, QKV_SMEM);
    cudaFuncSetAttribute(attn,   cudaFuncAttributeMaxDynamicSharedMemorySize, A_SMEM);

    prep_x<<<4096, 256>>>(X);
    prep_w<<<dim3(32, 2, 48), dim3(32, 8)>>>(Wq, Wk, Wv);
    qkv_mm<<<dim3(32, 16, 3), 256, QKV_SMEM>>>(bq, bk, bv);
    attn<<<512, 256, A_SMEM>>>((float*)d_out);
}

// round 10
// speedup vs baseline: 1.0858x; 1.0735x over previous
#include <cuda_runtime.h>
#include <cuda_bf16.h>
#include <cstdint>

// ---------------- scratch (device globals) ----------------
__device__ __align__(16) __nv_bfloat16 g_Xh[4096*1024], g_Xl[4096*1024];
__device__ __align__(16) __nv_bfloat16 g_Wh[3*1024*1024], g_Wl[3*1024*1024];
__device__ __align__(16) __nv_bfloat16 g_Qh[32*2048*64], g_Ql[32*2048*64];
__device__ __align__(16) __nv_bfloat16 g_Kh[32*2048*64], g_Kl[32*2048*64];
__device__ __align__(16) __nv_bfloat16 g_Vh[32*2048*64], g_Vl[32*2048*64];

// ---------------- helpers ----------------
__device__ __forceinline__ uint32_t smem_u32(const void* p) {
    uint32_t a;
    asm("{ .reg .u64 t; cvta.to.shared.u64 t, %1; cvt.u32.u64 %0, t; }" : "=r"(a) : "l"(p));
    return a;
}
// truncation-based hi/lo split (shift/mask + 1 FSUB per value)
__device__ __forceinline__ void split2(float a, float b, uint32_t& hw, uint32_t& lw) {
    uint32_t ua = __float_as_uint(a), ub = __float_as_uint(b);
    hw = (ua >> 16) | (ub & 0xFFFF0000u);
    float la = a - __uint_as_float(ua & 0xFFFF0000u);
    float lb = b - __uint_as_float(ub & 0xFFFF0000u);
    lw = (__float_as_uint(la) >> 16) | (__float_as_uint(lb) & 0xFFFF0000u);
}
__device__ __forceinline__ float fast_exp(float x) {
    float y = fmaxf(x * 1.4426950408889634f, -100.0f);
    float z = y + 12582912.0f;
    int   n = __float_as_int(z) - 0x4B400000;
    float f = y - (z - 12582912.0f);
    float p = 1.33335581e-3f;
    p = fmaf(p, f, 9.61812911e-3f);
    p = fmaf(p, f, 5.55041087e-2f);
    p = fmaf(p, f, 2.40226507e-1f);
    p = fmaf(p, f, 6.93147181e-1f);
    p = fmaf(p, f, 1.0f);
    return __int_as_float(__float_as_int(p) + (n << 23));
}
__device__ __forceinline__ void ldsm_x4(uint32_t a, uint32_t& r0, uint32_t& r1,
                                        uint32_t& r2, uint32_t& r3) {
    asm volatile("ldmatrix.sync.aligned.m8n8.x4.shared.b16 {%0,%1,%2,%3}, [%4];"
        : "=r"(r0), "=r"(r1), "=r"(r2), "=r"(r3) : "r"(a));
}
__device__ __forceinline__ void ldsm_x4t(uint32_t a, uint32_t& r0, uint32_t& r1,
                                         uint32_t& r2, uint32_t& r3) {
    asm volatile("ldmatrix.sync.aligned.m8n8.x4.trans.shared.b16 {%0,%1,%2,%3}, [%4];"
        : "=r"(r0), "=r"(r1), "=r"(r2), "=r"(r3) : "r"(a));
}
__device__ __forceinline__ void mma16816(float* c, const uint32_t* a,
                                         uint32_t b0, uint32_t b1) {
    asm("mma.sync.aligned.m16n8k16.row.col.f32.bf16.bf16.f32 "
        "{%0,%1,%2,%3}, {%4,%5,%6,%7}, {%8,%9}, {%0,%1,%2,%3};"
        : "+f"(c[0]), "+f"(c[1]), "+f"(c[2]), "+f"(c[3])
        : "r"(a[0]), "r"(a[1]), "r"(a[2]), "r"(a[3]), "r"(b0), "r"(b1));
}
__device__ __forceinline__ void cpa16(uint32_t dst, const void* src) {
    asm volatile("cp.async.cg.shared.global [%0], [%1], 16;" :: "r"(dst), "l"(src));
}
__device__ __forceinline__ void cpcommit() { asm volatile("cp.async.commit_group;"); }
__device__ __forceinline__ void cpwait1()  { asm volatile("cp.async.wait_group 1;"); }
__device__ __forceinline__ void cpwait0()  { asm volatile("cp.async.wait_group 0;"); }

// swizzled byte offset within an 8KB region (64 rows x 128B), chunk c8 in 0..7
__device__ __forceinline__ uint32_t swoff(int r, int c8) {
    return (uint32_t)(((r << 3) + (c8 ^ (r & 7))) << 4);
}

// ---------------- prep: split X ----------------
__global__ __launch_bounds__(256) void prep_x(const float* __restrict__ X) {
    size_t i = (size_t)blockIdx.x * 256 + threadIdx.x;
    float4 v = ((const float4*)X)[i];
    uint32_t h0, l0, h1, l1;
    split2(v.x, v.y, h0, l0);
    split2(v.z, v.w, h1, l1);
    ((uint2*)g_Xh)[i] = make_uint2(h0, h1);
    ((uint2*)g_Xl)[i] = make_uint2(l0, l1);
}

// ---------------- prep: transpose+split W -> [mat][h*64+e][d] ----------------
__global__ __launch_bounds__(256) void prep_w(const float* __restrict__ Wq,
                                              const float* __restrict__ Wk,
                                              const float* __restrict__ Wv) {
    int z = blockIdx.z, mat = z >> 4, h = z & 15;
    const float* W = (mat == 0 ? Wq : (mat == 1 ? Wk : Wv)) + (size_t)h * 1024 * 64;
    __shared__ float t[32][33];
    int d0 = blockIdx.x * 32, e0 = blockIdx.y * 32;
    int tx = threadIdx.x, ty = threadIdx.y;
    #pragma unroll
    for (int k = 0; k < 4; k++)
        t[ty + 8 * k][tx] = W[(size_t)(d0 + ty + 8 * k) * 64 + e0 + tx];
    __syncthreads();
    __nv_bfloat16* oh = g_Wh + (size_t)mat * 1048576;
    __nv_bfloat16* ol = g_Wl + (size_t)mat * 1048576;
    #pragma unroll
    for (int k = 0; k < 4; k++) {
        int j = ty + 8 * k;
        float v = t[tx][j];
        uint32_t uv = __float_as_uint(v);
        float hv = __uint_as_float(uv & 0xFFFF0000u);
        size_t o = (size_t)(h * 64 + e0 + j) * 1024 + d0 + tx;
        *(uint16_t*)&oh[o] = (uint16_t)(uv >> 16);
        *(uint16_t*)&ol[o] = (uint16_t)(__float_as_uint(v - hv) >> 16);
    }
}

// ---------------- QKV GEMM: 128x128 CTA tile, cp.async double buffer ----------------
// stage (32KB): A 2 regions (rows 0-63, 64-127) then B 2 regions (cols 0-63, 64-127).
// each region row: [h chunks c8=0..3 | l chunks c8=4..7], 32 k-values per half.
#define QS_STAGE 32768
#define QKV_SMEM (2 * QS_STAGE)

__device__ __forceinline__ void qkv_prefetch(uint32_t s0, int stile, int octile,
                                             int kc, int tid,
                                             const __nv_bfloat16* Bh,
                                             const __nv_bfloat16* Bl) {
    #pragma unroll
    for (int i = tid; i < 2048; i += 256) {
        int idx = i & 1023;
        int r = idx >> 3, c8 = idx & 7;
        bool isB = (i >= 1024);
        bool isH = (c8 < 4);
        const __nv_bfloat16* src = isB ? (isH ? Bh : Bl) : (isH ? g_Xh : g_Xl);
        int gr = (isB ? octile : stile) * 128 + r;
        size_t g = (size_t)gr * 1024 + kc * 32 + (c8 & 3) * 8;
        uint32_t d = s0 + (isB ? 16384u : 0u) + ((r >= 64) ? 8192u : 0u) + swoff(r & 63, c8);
        cpa16(d, src + g);
    }
}

__global__ __launch_bounds__(256, 2) void qkv_mm(const float* __restrict__ bq,
                                                 const float* __restrict__ bk,
                                                 const float* __restrict__ bv) {
    extern __shared__ __align__(16) __nv_bfloat16 smq[];
    uint32_t sb = smem_u32(smq);
    int tid = threadIdx.x, lane = tid & 31, wid = tid >> 5;
    int stile = blockIdx.x, octile = blockIdx.y, mat = blockIdx.z;
    int wm = wid >> 1, wn = wid & 1;   // 4x2 warps: 32 rows x 64 cols each
    int lm = lane & 15;

    const __nv_bfloat16* Bh = g_Wh + (size_t)mat * 1048576;
    const __nv_bfloat16* Bl = g_Wl + (size_t)mat * 1048576;

    float C[2][8][4] = {};

    qkv_prefetch(sb, stile, octile, 0, tid, Bh, Bl);
    cpcommit();

    for (int kc = 0; kc < 32; kc++) {
        if (kc < 31) {
            qkv_prefetch(sb + ((kc + 1) & 1) * QS_STAGE, stile, octile, kc + 1, tid, Bh, Bl);
            cpcommit();
            cpwait1();
        } else {
            cpwait0();
        }
        __syncthreads();
        uint32_t sA = sb + (kc & 1) * QS_STAGE;
        uint32_t sB = sA + 16384;

        #pragma unroll
        for (int ks = 0; ks < 2; ks++) {
            uint32_t ah[2][4], al[2][4];
            #pragma unroll
            for (int mt = 0; mt < 2; mt++) {
                int r = wm * 32 + mt * 16 + lm;
                uint32_t reg0 = (r >= 64) ? 8192u : 0u;
                int rr = r & 63;
                int c8 = ks * 2 + (lane >> 4);
                ldsm_x4(sA + reg0 + swoff(rr, c8),
                        ah[mt][0], ah[mt][1], ah[mt][2], ah[mt][3]);
                ldsm_x4(sA + reg0 + swoff(rr, 4 + c8),
                        al[mt][0], al[mt][1], al[mt][2], al[mt][3]);
            }
            #pragma unroll
            for (int ntp = 0; ntp < 4; ntp++) {
                int rB = ntp * 16 + ((lane >> 4) << 3) + (lane & 7);
                int c8 = ks * 2 + ((lane >> 3) & 1);
                uint32_t regB = wn * 8192u;
                uint32_t h0, h1, h2, h3, l0, l1, l2, l3;
                ldsm_x4(sB + regB + swoff(rB, c8),     h0, h1, h2, h3);
                ldsm_x4(sB + regB + swoff(rB, 4 + c8), l0, l1, l2, l3);
                #pragma unroll
                for (int mt = 0; mt < 2; mt++) {
                    mma16816(C[mt][2 * ntp],     ah[mt], h0, h1);
                    mma16816(C[mt][2 * ntp],     ah[mt], l0, l1);
                    mma16816(C[mt][2 * ntp],     al[mt], h0, h1);
                    mma16816(C[mt][2 * ntp + 1], ah[mt], h2, h3);
                    mma16816(C[mt][2 * ntp + 1], ah[mt], l2, l3);
                    mma16816(C[mt][2 * ntp + 1], al[mt], h2, h3);
                }
            }
        }
        __syncthreads();
    }

    const float* bias = (mat == 0 ? bq : (mat == 1 ? bk : bv));
    float scale = (mat == 0) ? 0.125f : 1.0f;
    __nv_bfloat16* Dh = (mat == 0 ? g_Qh : (mat == 1 ? g_Kh : g_Vh));
    __nv_bfloat16* Dl = (mat == 0 ? g_Ql : (mat == 1 ? g_Kl : g_Vl));
    #pragma unroll
    for (int mt = 0; mt < 2; mt++) {
        #pragma unroll
        for (int nt = 0; nt < 8; nt++) {
            int col = octile * 128 + wn * 64 + nt * 8 + 2 * (lane & 3);
            float b0 = __ldg(bias + col), b1 = __ldg(bias + col + 1);
            int hh = col >> 6, e = col & 63;
            #pragma unroll
            for (int hf = 0; hf < 2; hf++) {
                int row = stile * 128 + wm * 32 + mt * 16 + (lane >> 2) + 8 * hf;
                float v0 = (C[mt][nt][2 * hf + 0] + b0) * scale;
                float v1 = (C[mt][nt][2 * hf + 1] + b1) * scale;
                uint32_t hw, lw;
                split2(v0, v1, hw, lw);
                int b = row >> 11, s = row & 2047;
                size_t o = ((size_t)(b * 16 + hh) * 2048 + s) * 64 + e;
                *(uint32_t*)&Dh[o] = hw;
                *(uint32_t*)&Dl[o] = lw;
            }
        }
    }
}

// ---------------- attention: unchanged from R9 (best: 243.8us) ----------------
#define REG 8192
#define STAGE (4 * REG)
#define A_SMEM (2 * STAGE)

__device__ __forceinline__ void attn_prefetch(uint32_t s0, int tid,
                                              const __nv_bfloat16* Kh,
                                              const __nv_bfloat16* Kl,
                                              const __nv_bfloat16* Vh,
                                              const __nv_bfloat16* Vl, bool full) {
    #pragma unroll
    for (int i = tid; i < 512; i += 256) {
        int r = i >> 3, c8 = i & 7;
        uint32_t d = swoff(r, c8);
        size_t g = (size_t)r * 64 + c8 * 8;
        cpa16(s0 + d, Kh + g);
        if (full) {
            cpa16(s0 + REG + d,     Kl + g);
            cpa16(s0 + 2 * REG + d, Vh + g);
            cpa16(s0 + 3 * REG + d, Vl + g);
        }
    }
}

__device__ __forceinline__ void compS(uint32_t sK, uint32_t sKl, int k2, int lane,
                                      const uint32_t qh[4][4], const uint32_t ql[4][4],
                                      bool full, float S[2][4]) {
    #pragma unroll
    for (int z = 0; z < 4; z++) { S[0][z] = 0.f; S[1][z] = 0.f; }
    #pragma unroll
    for (int ks = 0; ks < 4; ks++) {
        int row = k2 * 16 + ((lane >> 4) << 3) + (lane & 7);
        int c8 = ks * 2 + ((lane >> 3) & 1);
        uint32_t d = swoff(row, c8);
        uint32_t h0, h1, h2, h3;
        ldsm_x4(sK + d, h0, h1, h2, h3);
        if (full) {
            uint32_t l0, l1, l2, l3;
            ldsm_x4(sKl + d, l0, l1, l2, l3);
            mma16816(S[0], qh[ks], h0, h1);
            mma16816(S[0], qh[ks], l0, l1);
            mma16816(S[0], ql[ks], h0, h1);
            mma16816(S[1], qh[ks], h2, h3);
            mma16816(S[1], qh[ks], l2, l3);
            mma16816(S[1], ql[ks], h2, h3);
        } else {
            mma16816(S[0], qh[ks], h0, h1);
            mma16816(S[1], qh[ks], h2, h3);
        }
    }
}

__global__ __launch_bounds__(256, 2) void attn(float* __restrict__ out) {
    extern __shared__ __align__(16) char sm[];
    uint32_t sb = smem_u32(sm);
    int tid = threadIdx.x, lane = tid & 31, w = tid >> 5;
    int bh = blockIdx.x >> 4, qt = 15 - (blockIdx.x & 15);
    int b = bh >> 4, h = bh & 15;
    int lm = lane & 15;

    const __nv_bfloat16* Qh = g_Qh + ((size_t)bh * 2048 + qt * 128) * 64;
    const __nv_bfloat16* Ql = g_Ql + ((size_t)bh * 2048 + qt * 128) * 64;
    #pragma unroll
    for (int i = tid; i < 1024; i += 256) {
        int r = i >> 3, c8 = i & 7;
        uint32_t d = ((r >= 64) ? REG : 0) + swoff(r & 63, c8);
        size_t g = (size_t)r * 64 + c8 * 8;
        cpa16(sb + d,           Qh + g);
        cpa16(sb + 2 * REG + d, Ql + g);
    }
    cpcommit(); cpwait0();
    __syncthreads();

    uint32_t qh[4][4], ql[4][4];
    {
        int r = w * 16 + lm;
        uint32_t qreg = (r >= 64) ? REG : 0;
        int rr = r & 63;
        #pragma unroll
        for (int ks = 0; ks < 4; ks++) {
            int c8 = ks * 2 + (lane >> 4);
            uint32_t d = swoff(rr, c8);
            ldsm_x4(sb + qreg + d,           qh[ks][0], qh[ks][1], qh[ks][2], qh[ks][3]);
            ldsm_x4(sb + qreg + 2 * REG + d, ql[ks][0], ql[ks][1], ql[ks][2], ql[ks][3]);
        }
    }
    __syncthreads();

    const __nv_bfloat16* Khb = g_Kh + (size_t)bh * 2048 * 64;
    const __nv_bfloat16* Klb = g_Kl + (size_t)bh * 2048 * 64;
    const __nv_bfloat16* Vhb = g_Vh + (size_t)bh * 2048 * 64;
    const __nv_bfloat16* Vlb = g_Vl + (size_t)bh * 2048 * 64;

    int kmax = 2 * qt + 1;
    attn_prefetch(sb, tid, Khb, Klb, Vhb, Vlb, true);
    cpcommit();

    float O[8][4] = {};
    float lsum[2] = {};
    int rbase = qt * 128 + w * 16 + (lane >> 2);

    for (int kt = 0; kt < 32; kt++) {
        if (kt < 31) {
            size_t off = (size_t)(kt + 1) * 64 * 64;
            attn_prefetch(sb + ((kt + 1) & 1) * STAGE, tid,
                          Khb + off, Klb + off, Vhb + off, Vlb + off, (kt + 1) <= kmax);
            cpcommit();
            cpwait1();
        } else {
            cpwait0();
        }
        __syncthreads();

        uint32_t sK = sb + (kt & 1) * STAGE;
        uint32_t sKl = sK + REG, sV = sK + 2 * REG, sVl = sK + 3 * REG;
        bool live = (kt <= kmax);
        int cb = kt * 64 + 2 * (lane & 3);

        float Sc[2][4];
        compS(sK, sKl, 0, lane, qh, ql, live, Sc);

        #pragma unroll
        for (int k2 = 0; k2 < 4; k2++) {
            float Sn[2][4];
            if (k2 < 3) compS(sK, sKl, k2 + 1, lane, qh, ql, live, Sn);

            #pragma unroll
            for (int ntl = 0; ntl < 2; ntl++) {
                int colg = cb + k2 * 16 + ntl * 8;
                #pragma unroll
                for (int hf = 0; hf < 2; hf++) {
                    int rg = rbase + 8 * hf;
                    float e0 = fast_exp(Sc[ntl][2 * hf + 0]);
                    float e1 = fast_exp(Sc[ntl][2 * hf + 1]);
                    lsum[hf] += e0 + e1;
                    Sc[ntl][2 * hf + 0] = (colg     <= rg) ? e0 : 0.f;
                    Sc[ntl][2 * hf + 1] = (colg + 1 <= rg) ? e1 : 0.f;
                }
            }
            if (live) {
                uint32_t pah[4], pal[4];
                split2(Sc[0][0], Sc[0][1], pah[0], pal[0]);
                split2(Sc[0][2], Sc[0][3], pah[1], pal[1]);
                split2(Sc[1][0], Sc[1][1], pah[2], pal[2]);
                split2(Sc[1][2], Sc[1][3], pah[3], pal[3]);
                int row = k2 * 16 + lm;
                uint32_t vA[8];
                {
                    uint32_t d = swoff(row, (lane >> 4));
                    ldsm_x4t(sV + d,  vA[0], vA[1], vA[2], vA[3]);
                    ldsm_x4t(sVl + d, vA[4], vA[5], vA[6], vA[7]);
                }
                #pragma unroll
                for (int ntp = 0; ntp < 4; ntp++) {
                    uint32_t vB[8];
                    if (ntp < 3) {
                        uint32_t d = swoff(row, (ntp + 1) * 2 + (lane >> 4));
                        ldsm_x4t(sV + d,  vB[0], vB[1], vB[2], vB[3]);
                        ldsm_x4t(sVl + d, vB[4], vB[5], vB[6], vB[7]);
                    }
                    mma16816(O[2 * ntp],     pah, vA[0], vA[1]);
                    mma16816(O[2 * ntp],     pah, vA[4], vA[5]);
                    mma16816(O[2 * ntp],     pal, vA[0], vA[1]);
                    mma16816(O[2 * ntp + 1], pah, vA[2], vA[3]);
                    mma16816(O[2 * ntp + 1], pah, vA[6], vA[7]);
                    mma16816(O[2 * ntp + 1], pal, vA[2], vA[3]);
                    if (ntp < 3) {
                        #pragma unroll
                        for (int z = 0; z < 8; z++) vA[z] = vB[z];
                    }
                }
            }
            if (k2 < 3) {
                #pragma unroll
                for (int ntl = 0; ntl < 2; ntl++)
                    #pragma unroll
                    for (int z = 0; z < 4; z++) Sc[ntl][z] = Sn[ntl][z];
            }
        }
        __syncthreads();
    }

    #pragma unroll
    for (int hf = 0; hf < 2; hf++) {
        lsum[hf] += __shfl_xor_sync(0xffffffffu, lsum[hf], 1);
        lsum[hf] += __shfl_xor_sync(0xffffffffu, lsum[hf], 2);
    }

    #pragma unroll
    for (int hf = 0; hf < 2; hf++) {
        float inv = 1.0f / lsum[hf];
        int rg = rbase + 8 * hf;
        float* ob = out + ((size_t)b * 2048 + rg) * 1024 + h * 64;
        #pragma unroll
        for (int nt = 0; nt < 8; nt++) {
            int c = nt * 8 + 2 * (lane & 3);
            *(float2*)&ob[c] = make_float2(O[nt][2 * hf] * inv, O[nt][2 * hf + 1] * inv);
        }
    }
}

extern "C" void kernel_launch(void* const* d_in, const int* in_sizes, int n_in,
                              void* d_out, int out_size) {
    const float* X  = (const float*)d_in[0];
    const float* Wq = (const float*)d_in[1];
    const float* bq = (const float*)d_in[2];
    const float* Wk = (const float*)d_in[3];
    const float* bk = (const float*)d_in[4];
    const float* Wv = (const float*)d_in[5];
    const float* bv = (const float*)d_in[6];

    cudaFuncSetAttribute(qkv_mm, cudaFuncAttributeMaxDynamicSharedMemorySize, QKV_SMEM);
    cudaFuncSetAttribute(attn,   cudaFuncAttributeMaxDynamicSharedMemorySize, A_SMEM);

    prep_x<<<4096, 256>>>(X);
    prep_w<<<dim3(32, 2, 48), dim3(32, 8)>>>(Wq, Wk, Wv);
    qkv_mm<<<dim3(32, 8, 3), 256, QKV_SMEM>>>(bq, bk, bv);
    attn<<<512, 256, A_SMEM>>>((float*)d_out);
}

// round 11
// speedup vs baseline: 1.1869x; 1.0931x over previous
#include <cuda_runtime.h>
#include <cuda_bf16.h>
#include <cstdint>

// ---------------- scratch (device globals) ----------------
__device__ __align__(16) __nv_bfloat16 g_Xh[4096*1024], g_Xl[4096*1024];
__device__ __align__(16) __nv_bfloat16 g_Wh[3*1024*1024], g_Wl[3*1024*1024];
__device__ __align__(16) __nv_bfloat16 g_Qh[32*2048*64], g_Ql[32*2048*64];
__device__ __align__(16) __nv_bfloat16 g_Kh[32*2048*64], g_Kl[32*2048*64];
__device__ __align__(16) __nv_bfloat16 g_Vh[32*2048*64], g_Vl[32*2048*64];

// ---------------- helpers ----------------
__device__ __forceinline__ uint32_t smem_u32(const void* p) {
    uint32_t a;
    asm("{ .reg .u64 t; cvta.to.shared.u64 t, %1; cvt.u32.u64 %0, t; }" : "=r"(a) : "l"(p));
    return a;
}
// truncation-based hi/lo split (shift/mask + 1 FSUB per value)
__device__ __forceinline__ void split2(float a, float b, uint32_t& hw, uint32_t& lw) {
    uint32_t ua = __float_as_uint(a), ub = __float_as_uint(b);
    hw = (ua >> 16) | (ub & 0xFFFF0000u);
    float la = a - __uint_as_float(ua & 0xFFFF0000u);
    float lb = b - __uint_as_float(ub & 0xFFFF0000u);
    lw = (__float_as_uint(la) >> 16) | (__float_as_uint(lb) & 0xFFFF0000u);
}
__device__ __forceinline__ void ldsm_x4(uint32_t a, uint32_t& r0, uint32_t& r1,
                                        uint32_t& r2, uint32_t& r3) {
    asm volatile("ldmatrix.sync.aligned.m8n8.x4.shared.b16 {%0,%1,%2,%3}, [%4];"
        : "=r"(r0), "=r"(r1), "=r"(r2), "=r"(r3) : "r"(a));
}
__device__ __forceinline__ void ldsm_x4t(uint32_t a, uint32_t& r0, uint32_t& r1,
                                         uint32_t& r2, uint32_t& r3) {
    asm volatile("ldmatrix.sync.aligned.m8n8.x4.trans.shared.b16 {%0,%1,%2,%3}, [%4];"
        : "=r"(r0), "=r"(r1), "=r"(r2), "=r"(r3) : "r"(a));
}
__device__ __forceinline__ void mma16816(float* c, const uint32_t* a,
                                         uint32_t b0, uint32_t b1) {
    asm("mma.sync.aligned.m16n8k16.row.col.f32.bf16.bf16.f32 "
        "{%0,%1,%2,%3}, {%4,%5,%6,%7}, {%8,%9}, {%0,%1,%2,%3};"
        : "+f"(c[0]), "+f"(c[1]), "+f"(c[2]), "+f"(c[3])
        : "r"(a[0]), "r"(a[1]), "r"(a[2]), "r"(a[3]), "r"(b0), "r"(b1));
}
__device__ __forceinline__ void cpa16(uint32_t dst, const void* src) {
    asm volatile("cp.async.cg.shared.global [%0], [%1], 16;" :: "r"(dst), "l"(src));
}
__device__ __forceinline__ void cpcommit() { asm volatile("cp.async.commit_group;"); }
__device__ __forceinline__ void cpwait1()  { asm volatile("cp.async.wait_group 1;"); }
__device__ __forceinline__ void cpwait0()  { asm volatile("cp.async.wait_group 0;"); }

// swizzled byte offset within an 8KB region (64 rows x 128B), chunk c8 in 0..7
__device__ __forceinline__ uint32_t swoff(int r, int c8) {
    return (uint32_t)(((r << 3) + (c8 ^ (r & 7))) << 4);
}

// ---------------- prep: split X ----------------
__global__ __launch_bounds__(256) void prep_x(const float* __restrict__ X) {
    size_t i = (size_t)blockIdx.x * 256 + threadIdx.x;
    float4 v = ((const float4*)X)[i];
    uint32_t h0, l0, h1, l1;
    split2(v.x, v.y, h0, l0);
    split2(v.z, v.w, h1, l1);
    ((uint2*)g_Xh)[i] = make_uint2(h0, h1);
    ((uint2*)g_Xl)[i] = make_uint2(l0, l1);
}

// ---------------- prep: transpose+split W -> [mat][h*64+e][d] ----------------
__global__ __launch_bounds__(256) void prep_w(const float* __restrict__ Wq,
                                              const float* __restrict__ Wk,
                                              const float* __restrict__ Wv) {
    int z = blockIdx.z, mat = z >> 4, h = z & 15;
    const float* W = (mat == 0 ? Wq : (mat == 1 ? Wk : Wv)) + (size_t)h * 1024 * 64;
    __shared__ float t[32][33];
    int d0 = blockIdx.x * 32, e0 = blockIdx.y * 32;
    int tx = threadIdx.x, ty = threadIdx.y;
    #pragma unroll
    for (int k = 0; k < 4; k++)
        t[ty + 8 * k][tx] = W[(size_t)(d0 + ty + 8 * k) * 64 + e0 + tx];
    __syncthreads();
    __nv_bfloat16* oh = g_Wh + (size_t)mat * 1048576;
    __nv_bfloat16* ol = g_Wl + (size_t)mat * 1048576;
    #pragma unroll
    for (int k = 0; k < 4; k++) {
        int j = ty + 8 * k;
        float v = t[tx][j];
        uint32_t uv = __float_as_uint(v);
        float hv = __uint_as_float(uv & 0xFFFF0000u);
        size_t o = (size_t)(h * 64 + e0 + j) * 1024 + d0 + tx;
        *(uint16_t*)&oh[o] = (uint16_t)(uv >> 16);
        *(uint16_t*)&ol[o] = (uint16_t)(__float_as_uint(v - hv) >> 16);
    }
}

// ---------------- QKV GEMM: 128x128 CTA tile, cp.async double buffer ----------------
#define QS_STAGE 32768
#define QKV_SMEM (2 * QS_STAGE)

__device__ __forceinline__ void qkv_prefetch(uint32_t s0, int stile, int octile,
                                             int kc, int tid,
                                             const __nv_bfloat16* Bh,
                                             const __nv_bfloat16* Bl) {
    #pragma unroll
    for (int i = tid; i < 2048; i += 256) {
        int idx = i & 1023;
        int r = idx >> 3, c8 = idx & 7;
        bool isB = (i >= 1024);
        bool isH = (c8 < 4);
        const __nv_bfloat16* src = isB ? (isH ? Bh : Bl) : (isH ? g_Xh : g_Xl);
        int gr = (isB ? octile : stile) * 128 + r;
        size_t g = (size_t)gr * 1024 + kc * 32 + (c8 & 3) * 8;
        uint32_t d = s0 + (isB ? 16384u : 0u) + ((r >= 64) ? 8192u : 0u) + swoff(r & 63, c8);
        cpa16(d, src + g);
    }
}

__global__ __launch_bounds__(256, 2) void qkv_mm(const float* __restrict__ bq,
                                                 const float* __restrict__ bk,
                                                 const float* __restrict__ bv) {
    extern __shared__ __align__(16) __nv_bfloat16 smq[];
    uint32_t sb = smem_u32(smq);
    int tid = threadIdx.x, lane = tid & 31, wid = tid >> 5;
    int stile = blockIdx.x, octile = blockIdx.y, mat = blockIdx.z;
    int wm = wid >> 1, wn = wid & 1;   // 4x2 warps: 32 rows x 64 cols each
    int lm = lane & 15;

    const __nv_bfloat16* Bh = g_Wh + (size_t)mat * 1048576;
    const __nv_bfloat16* Bl = g_Wl + (size_t)mat * 1048576;

    float C[2][8][4] = {};

    qkv_prefetch(sb, stile, octile, 0, tid, Bh, Bl);
    cpcommit();

    for (int kc = 0; kc < 32; kc++) {
        if (kc < 31) {
            qkv_prefetch(sb + ((kc + 1) & 1) * QS_STAGE, stile, octile, kc + 1, tid, Bh, Bl);
            cpcommit();
            cpwait1();
        } else {
            cpwait0();
        }
        __syncthreads();
        uint32_t sA = sb + (kc & 1) * QS_STAGE;
        uint32_t sB = sA + 16384;

        #pragma unroll
        for (int ks = 0; ks < 2; ks++) {
            uint32_t ah[2][4], al[2][4];
            #pragma unroll
            for (int mt = 0; mt < 2; mt++) {
                int r = wm * 32 + mt * 16 + lm;
                uint32_t reg0 = (r >= 64) ? 8192u : 0u;
                int rr = r & 63;
                int c8 = ks * 2 + (lane >> 4);
                ldsm_x4(sA + reg0 + swoff(rr, c8),
                        ah[mt][0], ah[mt][1], ah[mt][2], ah[mt][3]);
                ldsm_x4(sA + reg0 + swoff(rr, 4 + c8),
                        al[mt][0], al[mt][1], al[mt][2], al[mt][3]);
            }
            #pragma unroll
            for (int ntp = 0; ntp < 4; ntp++) {
                int rB = ntp * 16 + ((lane >> 4) << 3) + (lane & 7);
                int c8 = ks * 2 + ((lane >> 3) & 1);
                uint32_t regB = wn * 8192u;
                uint32_t h0, h1, h2, h3, l0, l1, l2, l3;
                ldsm_x4(sB + regB + swoff(rB, c8),     h0, h1, h2, h3);
                ldsm_x4(sB + regB + swoff(rB, 4 + c8), l0, l1, l2, l3);
                #pragma unroll
                for (int mt = 0; mt < 2; mt++) {
                    mma16816(C[mt][2 * ntp],     ah[mt], h0, h1);
                    mma16816(C[mt][2 * ntp],     ah[mt], l0, l1);
                    mma16816(C[mt][2 * ntp],     al[mt], h0, h1);
                    mma16816(C[mt][2 * ntp + 1], ah[mt], h2, h3);
                    mma16816(C[mt][2 * ntp + 1], ah[mt], l2, l3);
                    mma16816(C[mt][2 * ntp + 1], al[mt], h2, h3);
                }
            }
        }
        __syncthreads();
    }

    const float* bias = (mat == 0 ? bq : (mat == 1 ? bk : bv));
    float scale = (mat == 0) ? 0.125f : 1.0f;
    __nv_bfloat16* Dh = (mat == 0 ? g_Qh : (mat == 1 ? g_Kh : g_Vh));
    __nv_bfloat16* Dl = (mat == 0 ? g_Ql : (mat == 1 ? g_Kl : g_Vl));
    #pragma unroll
    for (int mt = 0; mt < 2; mt++) {
        #pragma unroll
        for (int nt = 0; nt < 8; nt++) {
            int col = octile * 128 + wn * 64 + nt * 8 + 2 * (lane & 3);
            float b0 = __ldg(bias + col), b1 = __ldg(bias + col + 1);
            int hh = col >> 6, e = col & 63;
            #pragma unroll
            for (int hf = 0; hf < 2; hf++) {
                int row = stile * 128 + wm * 32 + mt * 16 + (lane >> 2) + 8 * hf;
                float v0 = (C[mt][nt][2 * hf + 0] + b0) * scale;
                float v1 = (C[mt][nt][2 * hf + 1] + b1) * scale;
                uint32_t hw, lw;
                split2(v0, v1, hw, lw);
                int b = row >> 11, s = row & 2047;
                size_t o = ((size_t)(b * 16 + hh) * 2048 + s) * 64 + e;
                *(uint32_t*)&Dh[o] = hw;
                *(uint32_t*)&Dl[o] = lw;
            }
        }
    }
}

// ---------------- attention: R10 structure, exp moved to MUFU (__expf) ----------------
#define REG 8192
#define STAGE (4 * REG)
#define A_SMEM (2 * STAGE)

__device__ __forceinline__ void attn_prefetch(uint32_t s0, int tid,
                                              const __nv_bfloat16* Kh,
                                              const __nv_bfloat16* Kl,
                                              const __nv_bfloat16* Vh,
                                              const __nv_bfloat16* Vl, bool full) {
    #pragma unroll
    for (int i = tid; i < 512; i += 256) {
        int r = i >> 3, c8 = i & 7;
        uint32_t d = swoff(r, c8);
        size_t g = (size_t)r * 64 + c8 * 8;
        cpa16(s0 + d, Kh + g);
        if (full) {
            cpa16(s0 + REG + d,     Kl + g);
            cpa16(s0 + 2 * REG + d, Vh + g);
            cpa16(s0 + 3 * REG + d, Vl + g);
        }
    }
}

__device__ __forceinline__ void compS(uint32_t sK, uint32_t sKl, int k2, int lane,
                                      const uint32_t qh[4][4], const uint32_t ql[4][4],
                                      bool full, float S[2][4]) {
    #pragma unroll
    for (int z = 0; z < 4; z++) { S[0][z] = 0.f; S[1][z] = 0.f; }
    #pragma unroll
    for (int ks = 0; ks < 4; ks++) {
        int row = k2 * 16 + ((lane >> 4) << 3) + (lane & 7);
        int c8 = ks * 2 + ((lane >> 3) & 1);
        uint32_t d = swoff(row, c8);
        uint32_t h0, h1, h2, h3;
        ldsm_x4(sK + d, h0, h1, h2, h3);
        if (full) {
            uint32_t l0, l1, l2, l3;
            ldsm_x4(sKl + d, l0, l1, l2, l3);
            mma16816(S[0], qh[ks], h0, h1);
            mma16816(S[0], qh[ks], l0, l1);
            mma16816(S[0], ql[ks], h0, h1);
            mma16816(S[1], qh[ks], h2, h3);
            mma16816(S[1], qh[ks], l2, l3);
            mma16816(S[1], ql[ks], h2, h3);
        } else {
            mma16816(S[0], qh[ks], h0, h1);
            mma16816(S[1], qh[ks], h2, h3);
        }
    }
}

__global__ __launch_bounds__(256, 2) void attn(float* __restrict__ out) {
    extern __shared__ __align__(16) char sm[];
    uint32_t sb = smem_u32(sm);
    int tid = threadIdx.x, lane = tid & 31, w = tid >> 5;
    int bh = blockIdx.x >> 4, qt = 15 - (blockIdx.x & 15);
    int b = bh >> 4, h = bh & 15;
    int lm = lane & 15;

    const __nv_bfloat16* Qh = g_Qh + ((size_t)bh * 2048 + qt * 128) * 64;
    const __nv_bfloat16* Ql = g_Ql + ((size_t)bh * 2048 + qt * 128) * 64;
    #pragma unroll
    for (int i = tid; i < 1024; i += 256) {
        int r = i >> 3, c8 = i & 7;
        uint32_t d = ((r >= 64) ? REG : 0) + swoff(r & 63, c8);
        size_t g = (size_t)r * 64 + c8 * 8;
        cpa16(sb + d,           Qh + g);
        cpa16(sb + 2 * REG + d, Ql + g);
    }
    cpcommit(); cpwait0();
    __syncthreads();

    uint32_t qh[4][4], ql[4][4];
    {
        int r = w * 16 + lm;
        uint32_t qreg = (r >= 64) ? REG : 0;
        int rr = r & 63;
        #pragma unroll
        for (int ks = 0; ks < 4; ks++) {
            int c8 = ks * 2 + (lane >> 4);
            uint32_t d = swoff(rr, c8);
            ldsm_x4(sb + qreg + d,           qh[ks][0], qh[ks][1], qh[ks][2], qh[ks][3]);
            ldsm_x4(sb + qreg + 2 * REG + d, ql[ks][0], ql[ks][1], ql[ks][2], ql[ks][3]);
        }
    }
    __syncthreads();

    const __nv_bfloat16* Khb = g_Kh + (size_t)bh * 2048 * 64;
    const __nv_bfloat16* Klb = g_Kl + (size_t)bh * 2048 * 64;
    const __nv_bfloat16* Vhb = g_Vh + (size_t)bh * 2048 * 64;
    const __nv_bfloat16* Vlb = g_Vl + (size_t)bh * 2048 * 64;

    int kmax = 2 * qt + 1;
    attn_prefetch(sb, tid, Khb, Klb, Vhb, Vlb, true);
    cpcommit();

    float O[8][4] = {};
    float lsum[2] = {};
    int rbase = qt * 128 + w * 16 + (lane >> 2);

    for (int kt = 0; kt < 32; kt++) {
        if (kt < 31) {
            size_t off = (size_t)(kt + 1) * 64 * 64;
            attn_prefetch(sb + ((kt + 1) & 1) * STAGE, tid,
                          Khb + off, Klb + off, Vhb + off, Vlb + off, (kt + 1) <= kmax);
            cpcommit();
            cpwait1();
        } else {
            cpwait0();
        }
        __syncthreads();

        uint32_t sK = sb + (kt & 1) * STAGE;
        uint32_t sKl = sK + REG, sV = sK + 2 * REG, sVl = sK + 3 * REG;
        bool live = (kt <= kmax);
        int cb = kt * 64 + 2 * (lane & 3);

        float Sc[2][4];
        compS(sK, sKl, 0, lane, qh, ql, live, Sc);

        #pragma unroll
        for (int k2 = 0; k2 < 4; k2++) {
            float Sn[2][4];
            if (k2 < 3) compS(sK, sKl, k2 + 1, lane, qh, ql, live, Sn);

            // ---- exp on MUFU (short chain, idle pipe) + full-row lsum + tril mask
            #pragma unroll
            for (int ntl = 0; ntl < 2; ntl++) {
                int colg = cb + k2 * 16 + ntl * 8;
                #pragma unroll
                for (int hf = 0; hf < 2; hf++) {
                    int rg = rbase + 8 * hf;
                    float e0 = __expf(Sc[ntl][2 * hf + 0]);
                    float e1 = __expf(Sc[ntl][2 * hf + 1]);
                    lsum[hf] += e0 + e1;
                    Sc[ntl][2 * hf + 0] = (colg     <= rg) ? e0 : 0.f;
                    Sc[ntl][2 * hf + 1] = (colg + 1 <= rg) ? e1 : 0.f;
                }
            }
            if (live) {
                uint32_t pah[4], pal[4];
                split2(Sc[0][0], Sc[0][1], pah[0], pal[0]);
                split2(Sc[0][2], Sc[0][3], pah[1], pal[1]);
                split2(Sc[1][0], Sc[1][1], pah[2], pal[2]);
                split2(Sc[1][2], Sc[1][3], pah[3], pal[3]);
                int row = k2 * 16 + lm;
                uint32_t vA[8];
                {
                    uint32_t d = swoff(row, (lane >> 4));
                    ldsm_x4t(sV + d,  vA[0], vA[1], vA[2], vA[3]);
                    ldsm_x4t(sVl + d, vA[4], vA[5], vA[6], vA[7]);
                }
                #pragma unroll
                for (int ntp = 0; ntp < 4; ntp++) {
                    uint32_t vB[8];
                    if (ntp < 3) {
                        uint32_t d = swoff(row, (ntp + 1) * 2 + (lane >> 4));
                        ldsm_x4t(sV + d,  vB[0], vB[1], vB[2], vB[3]);
                        ldsm_x4t(sVl + d, vB[4], vB[5], vB[6], vB[7]);
                    }
                    mma16816(O[2 * ntp],     pah, vA[0], vA[1]);
                    mma16816(O[2 * ntp],     pah, vA[4], vA[5]);
                    mma16816(O[2 * ntp],     pal, vA[0], vA[1]);
                    mma16816(O[2 * ntp + 1], pah, vA[2], vA[3]);
                    mma16816(O[2 * ntp + 1], pah, vA[6], vA[7]);
                    mma16816(O[2 * ntp + 1], pal, vA[2], vA[3]);
                    if (ntp < 3) {
                        #pragma unroll
                        for (int z = 0; z < 8; z++) vA[z] = vB[z];
                    }
                }
            }
            if (k2 < 3) {
                #pragma unroll
                for (int ntl = 0; ntl < 2; ntl++)
                    #pragma unroll
                    for (int z = 0; z < 4; z++) Sc[ntl][z] = Sn[ntl][z];
            }
        }
        __syncthreads();
    }

    #pragma unroll
    for (int hf = 0; hf < 2; hf++) {
        lsum[hf] += __shfl_xor_sync(0xffffffffu, lsum[hf], 1);
        lsum[hf] += __shfl_xor_sync(0xffffffffu, lsum[hf], 2);
    }

    #pragma unroll
    for (int hf = 0; hf < 2; hf++) {
        float inv = 1.0f / lsum[hf];
        int rg = rbase + 8 * hf;
        float* ob = out + ((size_t)b * 2048 + rg) * 1024 + h * 64;
        #pragma unroll
        for (int nt = 0; nt < 8; nt++) {
            int c = nt * 8 + 2 * (lane & 3);
            *(float2*)&ob[c] = make_float2(O[nt][2 * hf] * inv, O[nt][2 * hf + 1] * inv);
        }
    }
}

extern "C" void kernel_launch(void* const* d_in, const int* in_sizes, int n_in,
                              void* d_out, int out_size) {
    const float* X  = (const float*)d_in[0];
    const float* Wq = (const float*)d_in[1];
    const float* bq = (const float*)d_in[2];
    const float* Wk = (const float*)d_in[3];
    const float* bk = (const float*)d_in[4];
    const float* Wv = (const float*)d_in[5];
    const float* bv = (const float*)d_in[6];

    cudaFuncSetAttribute(qkv_mm, cudaFuncAttributeMaxDynamicSharedMemorySize, QKV_SMEM);
    cudaFuncSetAttribute(attn,   cudaFuncAttributeMaxDynamicSharedMemorySize, A_SMEM);

    prep_x<<<4096, 256>>>(X);
    prep_w<<<dim3(32, 2, 48), dim3(32, 8)>>>(Wq, Wk, Wv);
    qkv_mm<<<dim3(32, 8, 3), 256, QKV_SMEM>>>(bq, bk, bv);
    attn<<<512, 256, A_SMEM>>>((float*)d_out);
}

// round 12
// speedup vs baseline: 2.7843x; 2.3460x over previous
#include <cuda_runtime.h>
#include <cuda_fp16.h>
#include <cstdint>

// ---------------- scratch (device globals, fp16 single-term) ----------------
__device__ __align__(16) __half g_Xf[4096*1024];
__device__ __align__(16) __half g_Wf[3*1024*1024];
__device__ __align__(16) __half g_Qf[32*2048*64];
__device__ __align__(16) __half g_Kf[32*2048*64];
__device__ __align__(16) __half g_Vf[32*2048*64];

// ---------------- helpers ----------------
__device__ __forceinline__ uint32_t smem_u32(const void* p) {
    uint32_t a;
    asm("{ .reg .u64 t; cvta.to.shared.u64 t, %1; cvt.u32.u64 %0, t; }" : "=r"(a) : "l"(p));
    return a;
}
__device__ __forceinline__ uint32_t packh(float a, float b) {
    __half2 h = __floats2half2_rn(a, b);
    return *reinterpret_cast<uint32_t*>(&h);
}
__device__ __forceinline__ void ldsm_x4(uint32_t a, uint32_t& r0, uint32_t& r1,
                                        uint32_t& r2, uint32_t& r3) {
    asm volatile("ldmatrix.sync.aligned.m8n8.x4.shared.b16 {%0,%1,%2,%3}, [%4];"
        : "=r"(r0), "=r"(r1), "=r"(r2), "=r"(r3) : "r"(a));
}
__device__ __forceinline__ void ldsm_x4t(uint32_t a, uint32_t& r0, uint32_t& r1,
                                         uint32_t& r2, uint32_t& r3) {
    asm volatile("ldmatrix.sync.aligned.m8n8.x4.trans.shared.b16 {%0,%1,%2,%3}, [%4];"
        : "=r"(r0), "=r"(r1), "=r"(r2), "=r"(r3) : "r"(a));
}
__device__ __forceinline__ void mma16816(float* c, const uint32_t* a,
                                         uint32_t b0, uint32_t b1) {
    asm("mma.sync.aligned.m16n8k16.row.col.f32.f16.f16.f32 "
        "{%0,%1,%2,%3}, {%4,%5,%6,%7}, {%8,%9}, {%0,%1,%2,%3};"
        : "+f"(c[0]), "+f"(c[1]), "+f"(c[2]), "+f"(c[3])
        : "r"(a[0]), "r"(a[1]), "r"(a[2]), "r"(a[3]), "r"(b0), "r"(b1));
}
__device__ __forceinline__ void cpa16(uint32_t dst, const void* src) {
    asm volatile("cp.async.cg.shared.global [%0], [%1], 16;" :: "r"(dst), "l"(src));
}
__device__ __forceinline__ void cpcommit() { asm volatile("cp.async.commit_group;"); }
__device__ __forceinline__ void cpwait1()  { asm volatile("cp.async.wait_group 1;"); }
__device__ __forceinline__ void cpwait0()  { asm volatile("cp.async.wait_group 0;"); }

// swizzled byte offset within an 8KB region (64 rows x 128B), chunk c8 in 0..7
__device__ __forceinline__ uint32_t swoff(int r, int c8) {
    return (uint32_t)(((r << 3) + (c8 ^ (r & 7))) << 4);
}

// ---------------- prep: X fp32 -> fp16 ----------------
__global__ __launch_bounds__(256) void prep_x(const float* __restrict__ X) {
    size_t i = (size_t)blockIdx.x * 256 + threadIdx.x;   // 1M float4
    float4 v = ((const float4*)X)[i];
    ((uint2*)g_Xf)[i] = make_uint2(packh(v.x, v.y), packh(v.z, v.w));
}

// ---------------- prep: transpose W -> [mat][h*64+e][d], fp16 ----------------
__global__ __launch_bounds__(256) void prep_w(const float* __restrict__ Wq,
                                              const float* __restrict__ Wk,
                                              const float* __restrict__ Wv) {
    int z = blockIdx.z, mat = z >> 4, h = z & 15;
    const float* W = (mat == 0 ? Wq : (mat == 1 ? Wk : Wv)) + (size_t)h * 1024 * 64;
    __shared__ float t[32][33];
    int d0 = blockIdx.x * 32, e0 = blockIdx.y * 32;
    int tx = threadIdx.x, ty = threadIdx.y;
    #pragma unroll
    for (int k = 0; k < 4; k++)
        t[ty + 8 * k][tx] = W[(size_t)(d0 + ty + 8 * k) * 64 + e0 + tx];
    __syncthreads();
    __half* of = g_Wf + (size_t)mat * 1048576;
    #pragma unroll
    for (int k = 0; k < 4; k++) {
        int j = ty + 8 * k;
        of[(size_t)(h * 64 + e0 + j) * 1024 + d0 + tx] = __float2half(t[tx][j]);
    }
}

// ---------------- QKV GEMM: 128x128 CTA tile, fp16, k-chunk 64 ----------------
// stage (32KB): A region0 rows0-63 @0, A region1 @8192, B r0 @16384, B r1 @24576
#define QS_STAGE 32768
#define QKV_SMEM (2 * QS_STAGE)

__device__ __forceinline__ void qkv_prefetch(uint32_t s0, int stile, int octile,
                                             int kc, int tid, const __half* Bf) {
    #pragma unroll
    for (int i = tid; i < 2048; i += 256) {
        int idx = i & 1023;
        int r = idx >> 3, c8 = idx & 7;
        bool isB = (i >= 1024);
        const __half* src = isB ? Bf : g_Xf;
        int gr = (isB ? octile : stile) * 128 + r;
        size_t g = (size_t)gr * 1024 + kc * 64 + c8 * 8;
        uint32_t d = s0 + (isB ? 16384u : 0u) + ((r >= 64) ? 8192u : 0u) + swoff(r & 63, c8);
        cpa16(d, src + g);
    }
}

__global__ __launch_bounds__(256, 2) void qkv_mm(const float* __restrict__ bq,
                                                 const float* __restrict__ bk,
                                                 const float* __restrict__ bv) {
    extern __shared__ __align__(16) __half smq[];
    uint32_t sb = smem_u32(smq);
    int tid = threadIdx.x, lane = tid & 31, wid = tid >> 5;
    int stile = blockIdx.x, octile = blockIdx.y, mat = blockIdx.z;
    int wm = wid >> 1, wn = wid & 1;   // 4x2 warps: 32 rows x 64 cols each
    int lm = lane & 15;

    const __half* Bf = g_Wf + (size_t)mat * 1048576;

    float C[2][8][4] = {};

    qkv_prefetch(sb, stile, octile, 0, tid, Bf);
    cpcommit();

    for (int kc = 0; kc < 16; kc++) {
        if (kc < 15) {
            qkv_prefetch(sb + ((kc + 1) & 1) * QS_STAGE, stile, octile, kc + 1, tid, Bf);
            cpcommit();
            cpwait1();
        } else {
            cpwait0();
        }
        __syncthreads();
        uint32_t sA = sb + (kc & 1) * QS_STAGE;
        uint32_t sB = sA + 16384;

        #pragma unroll
        for (int ks = 0; ks < 4; ks++) {
            uint32_t af[2][4];
            #pragma unroll
            for (int mt = 0; mt < 2; mt++) {
                int r = wm * 32 + mt * 16 + lm;
                uint32_t reg0 = (r >= 64) ? 8192u : 0u;
                int c8 = ks * 2 + (lane >> 4);
                ldsm_x4(sA + reg0 + swoff(r & 63, c8),
                        af[mt][0], af[mt][1], af[mt][2], af[mt][3]);
            }
            #pragma unroll
            for (int ntp = 0; ntp < 4; ntp++) {
                int rB = ntp * 16 + ((lane >> 4) << 3) + (lane & 7);
                int c8 = ks * 2 + ((lane >> 3) & 1);
                uint32_t regB = wn * 8192u;
                uint32_t h0, h1, h2, h3;
                ldsm_x4(sB + regB + swoff(rB, c8), h0, h1, h2, h3);
                #pragma unroll
                for (int mt = 0; mt < 2; mt++) {
                    mma16816(C[mt][2 * ntp],     af[mt], h0, h1);
                    mma16816(C[mt][2 * ntp + 1], af[mt], h2, h3);
                }
            }
        }
        __syncthreads();
    }

    const float* bias = (mat == 0 ? bq : (mat == 1 ? bk : bv));
    float scale = (mat == 0) ? 0.125f : 1.0f;
    __half* Df = (mat == 0 ? g_Qf : (mat == 1 ? g_Kf : g_Vf));
    #pragma unroll
    for (int mt = 0; mt < 2; mt++) {
        #pragma unroll
        for (int nt = 0; nt < 8; nt++) {
            int col = octile * 128 + wn * 64 + nt * 8 + 2 * (lane & 3);
            float b0 = __ldg(bias + col), b1 = __ldg(bias + col + 1);
            int hh = col >> 6, e = col & 63;
            #pragma unroll
            for (int hf = 0; hf < 2; hf++) {
                int row = stile * 128 + wm * 32 + mt * 16 + (lane >> 2) + 8 * hf;
                float v0 = (C[mt][nt][2 * hf + 0] + b0) * scale;
                float v1 = (C[mt][nt][2 * hf + 1] + b1) * scale;
                int b = row >> 11, s = row & 2047;
                size_t o = ((size_t)(b * 16 + hh) * 2048 + s) * 64 + e;
                *(uint32_t*)&Df[o] = packh(v0, v1);
            }
        }
    }
}

// ---------------- attention: fp16 single-term, R11 skeleton ----------------
// smem: Q region0 @0, Q region1 @8192; stages @16384 + st*16384: K @+0, V @+8192
#define A_STAGE 16384
#define A_SMEM (16384 + 2 * A_STAGE)   // 48KB

__device__ __forceinline__ void attn_prefetch(uint32_t s0, int tid,
                                              const __half* Kf, const __half* Vf,
                                              bool full) {
    #pragma unroll
    for (int i = tid; i < 512; i += 256) {
        int r = i >> 3, c8 = i & 7;
        uint32_t d = swoff(r, c8);
        size_t g = (size_t)r * 64 + c8 * 8;
        cpa16(s0 + d, Kf + g);
        if (full) cpa16(s0 + 8192 + d, Vf + g);
    }
}

// S slice (16 rows x 16 cols), single fp16 term
__device__ __forceinline__ void compS(uint32_t sK, int k2, int lane,
                                      const uint32_t qf[4][4], float S[2][4]) {
    #pragma unroll
    for (int z = 0; z < 4; z++) { S[0][z] = 0.f; S[1][z] = 0.f; }
    #pragma unroll
    for (int ks = 0; ks < 4; ks++) {
        int row = k2 * 16 + ((lane >> 4) << 3) + (lane & 7);
        int c8 = ks * 2 + ((lane >> 3) & 1);
        uint32_t h0, h1, h2, h3;
        ldsm_x4(sK + swoff(row, c8), h0, h1, h2, h3);
        mma16816(S[0], qf[ks], h0, h1);
        mma16816(S[1], qf[ks], h2, h3);
    }
}

__global__ __launch_bounds__(256, 2) void attn(float* __restrict__ out) {
    extern __shared__ __align__(16) char sm[];
    uint32_t sb = smem_u32(sm);
    int tid = threadIdx.x, lane = tid & 31, w = tid >> 5;
    int bh = blockIdx.x >> 4, qt = 15 - (blockIdx.x & 15);   // heavy-first
    int b = bh >> 4, h = bh & 15;
    int lm = lane & 15;

    const __half* Qf  = g_Qf + ((size_t)bh * 2048 + qt * 128) * 64;
    const __half* Kfb = g_Kf + (size_t)bh * 2048 * 64;
    const __half* Vfb = g_Vf + (size_t)bh * 2048 * 64;

    // Q load (128x64 fp16, own region - never recycled)
    #pragma unroll
    for (int i = tid; i < 1024; i += 256) {
        int r = i >> 3, c8 = i & 7;
        uint32_t d = ((r >= 64) ? 8192u : 0u) + swoff(r & 63, c8);
        cpa16(sb + d, Qf + (size_t)r * 64 + c8 * 8);
    }
    cpcommit();

    int kmax = 2 * qt + 1;
    attn_prefetch(sb + 16384, tid, Kfb, Vfb, true);   // kt=0 always live
    cpcommit();

    cpwait1();          // Q group done
    __syncthreads();

    uint32_t qf[4][4];
    {
        int r = w * 16 + lm;
        uint32_t qreg = (r >= 64) ? 8192u : 0u;
        int rr = r & 63;
        #pragma unroll
        for (int ks = 0; ks < 4; ks++) {
            int c8 = ks * 2 + (lane >> 4);
            ldsm_x4(sb + qreg + swoff(rr, c8),
                    qf[ks][0], qf[ks][1], qf[ks][2], qf[ks][3]);
        }
    }

    float O[8][4] = {};
    float lsum[2] = {};
    int rbase = qt * 128 + w * 16 + (lane >> 2);

    for (int kt = 0; kt < 32; kt++) {
        if (kt < 31) {
            size_t off = (size_t)(kt + 1) * 64 * 64;
            attn_prefetch(sb + 16384 + ((kt + 1) & 1) * A_STAGE, tid,
                          Kfb + off, Vfb + off, (kt + 1) <= kmax);
            cpcommit();
            cpwait1();
        } else {
            cpwait0();
        }
        __syncthreads();

        uint32_t sK = sb + 16384 + (kt & 1) * A_STAGE;
        uint32_t sV = sK + 8192;
        bool live = (kt <= kmax);
        int cb = kt * 64 + 2 * (lane & 3);

        float Sc[2][4];
        compS(sK, 0, lane, qf, Sc);

        #pragma unroll
        for (int k2 = 0; k2 < 4; k2++) {
            // software pipeline: next slice's S MMAs overlap exp/PV of current
            float Sn[2][4];
            if (k2 < 3) compS(sK, k2 + 1, lane, qf, Sn);

            // ---- exp on MUFU + full-row lsum + post-softmax tril mask
            #pragma unroll
            for (int ntl = 0; ntl < 2; ntl++) {
                int colg = cb + k2 * 16 + ntl * 8;
                #pragma unroll
                for (int hf = 0; hf < 2; hf++) {
                    int rg = rbase + 8 * hf;
                    float e0 = __expf(Sc[ntl][2 * hf + 0]);
                    float e1 = __expf(Sc[ntl][2 * hf + 1]);
                    lsum[hf] += e0 + e1;
                    Sc[ntl][2 * hf + 0] = (colg     <= rg) ? e0 : 0.f;
                    Sc[ntl][2 * hf + 1] = (colg + 1 <= rg) ? e1 : 0.f;
                }
            }
            // ---- PV for this 16-wide k-slice (single fp16 term, V double-buffered)
            if (live) {
                uint32_t ph[4];
                ph[0] = packh(Sc[0][0], Sc[0][1]);
                ph[1] = packh(Sc[0][2], Sc[0][3]);
                ph[2] = packh(Sc[1][0], Sc[1][1]);
                ph[3] = packh(Sc[1][2], Sc[1][3]);
                int row = k2 * 16 + lm;
                uint32_t vA[4];
                ldsm_x4t(sV + swoff(row, (lane >> 4)), vA[0], vA[1], vA[2], vA[3]);
                #pragma unroll
                for (int ntp = 0; ntp < 4; ntp++) {
                    uint32_t vB[4];
                    if (ntp < 3)
                        ldsm_x4t(sV + swoff(row, (ntp + 1) * 2 + (lane >> 4)),
                                 vB[0], vB[1], vB[2], vB[3]);
                    mma16816(O[2 * ntp],     ph, vA[0], vA[1]);
                    mma16816(O[2 * ntp + 1], ph, vA[2], vA[3]);
                    if (ntp < 3) {
                        #pragma unroll
                        for (int z = 0; z < 4; z++) vA[z] = vB[z];
                    }
                }
            }
            if (k2 < 3) {
                #pragma unroll
                for (int ntl = 0; ntl < 2; ntl++)
                    #pragma unroll
                    for (int z = 0; z < 4; z++) Sc[ntl][z] = Sn[ntl][z];
            }
        }
        __syncthreads();   // compute done before next prefetch overwrites other stage
    }

    // ---- row denominators: quad butterfly (warp-local rows)
    #pragma unroll
    for (int hf = 0; hf < 2; hf++) {
        lsum[hf] += __shfl_xor_sync(0xffffffffu, lsum[hf], 1);
        lsum[hf] += __shfl_xor_sync(0xffffffffu, lsum[hf], 2);
    }

    // ---- write out
    #pragma unroll
    for (int hf = 0; hf < 2; hf++) {
        float inv = 1.0f / lsum[hf];
        int rg = rbase + 8 * hf;
        float* ob = out + ((size_t)b * 2048 + rg) * 1024 + h * 64;
        #pragma unroll
        for (int nt = 0; nt < 8; nt++) {
            int c = nt * 8 + 2 * (lane & 3);
            *(float2*)&ob[c] = make_float2(O[nt][2 * hf] * inv, O[nt][2 * hf + 1] * inv);
        }
    }
}

extern "C" void kernel_launch(void* const* d_in, const int* in_sizes, int n_in,
                              void* d_out, int out_size) {
    const float* X  = (const float*)d_in[0];
    const float* Wq = (const float*)d_in[1];
    const float* bq = (const float*)d_in[2];
    const float* Wk = (const float*)d_in[3];
    const float* bk = (const float*)d_in[4];
    const float* Wv = (const float*)d_in[5];
    const float* bv = (const float*)d_in[6];

    cudaFuncSetAttribute(qkv_mm, cudaFuncAttributeMaxDynamicSharedMemorySize, QKV_SMEM);
    cudaFuncSetAttribute(attn,   cudaFuncAttributeMaxDynamicSharedMemorySize, A_SMEM);

    prep_x<<<4096, 256>>>(X);
    prep_w<<<dim3(32, 2, 48), dim3(32, 8)>>>(Wq, Wk, Wv);
    qkv_mm<<<dim3(32, 8, 3), 256, QKV_SMEM>>>(bq, bk, bv);
    attn<<<512, 256, A_SMEM>>>((float*)d_out);
}

// round 13
// speedup vs baseline: 2.8184x; 1.0122x over previous
#include <cuda_runtime.h>
#include <cuda_fp16.h>
#include <cstdint>

// ---------------- scratch (device globals, fp16 single-term) ----------------
__device__ __align__(16) __half g_Xf[4096*1024];
__device__ __align__(16) __half g_Wf[3*1024*1024];
__device__ __align__(16) __half g_Qf[32*2048*64];
__device__ __align__(16) __half g_Kf[32*2048*64];
__device__ __align__(16) __half g_Vf[32*2048*64];

// ---------------- helpers ----------------
__device__ __forceinline__ uint32_t smem_u32(const void* p) {
    uint32_t a;
    asm("{ .reg .u64 t; cvta.to.shared.u64 t, %1; cvt.u32.u64 %0, t; }" : "=r"(a) : "l"(p));
    return a;
}
__device__ __forceinline__ uint32_t packh(float a, float b) {
    __half2 h = __floats2half2_rn(a, b);
    return *reinterpret_cast<uint32_t*>(&h);
}
__device__ __forceinline__ void ldsm_x4(uint32_t a, uint32_t& r0, uint32_t& r1,
                                        uint32_t& r2, uint32_t& r3) {
    asm volatile("ldmatrix.sync.aligned.m8n8.x4.shared.b16 {%0,%1,%2,%3}, [%4];"
        : "=r"(r0), "=r"(r1), "=r"(r2), "=r"(r3) : "r"(a));
}
__device__ __forceinline__ void ldsm_x4t(uint32_t a, uint32_t& r0, uint32_t& r1,
                                         uint32_t& r2, uint32_t& r3) {
    asm volatile("ldmatrix.sync.aligned.m8n8.x4.trans.shared.b16 {%0,%1,%2,%3}, [%4];"
        : "=r"(r0), "=r"(r1), "=r"(r2), "=r"(r3) : "r"(a));
}
__device__ __forceinline__ void mma16816(float* c, const uint32_t* a,
                                         uint32_t b0, uint32_t b1) {
    asm("mma.sync.aligned.m16n8k16.row.col.f32.f16.f16.f32 "
        "{%0,%1,%2,%3}, {%4,%5,%6,%7}, {%8,%9}, {%0,%1,%2,%3};"
        : "+f"(c[0]), "+f"(c[1]), "+f"(c[2]), "+f"(c[3])
        : "r"(a[0]), "r"(a[1]), "r"(a[2]), "r"(a[3]), "r"(b0), "r"(b1));
}
__device__ __forceinline__ void cpa16(uint32_t dst, const void* src) {
    asm volatile("cp.async.cg.shared.global [%0], [%1], 16;" :: "r"(dst), "l"(src));
}
__device__ __forceinline__ void cpcommit() { asm volatile("cp.async.commit_group;"); }
__device__ __forceinline__ void cpwait1()  { asm volatile("cp.async.wait_group 1;"); }
__device__ __forceinline__ void cpwait0()  { asm volatile("cp.async.wait_group 0;"); }

// swizzled byte offset within an 8KB region (64 rows x 128B), chunk c8 in 0..7
__device__ __forceinline__ uint32_t swoff(int r, int c8) {
    return (uint32_t)(((r << 3) + (c8 ^ (r & 7))) << 4);
}

// ---------------- prep: X fp32 -> fp16 ----------------
__global__ __launch_bounds__(256) void prep_x(const float* __restrict__ X) {
    size_t i = (size_t)blockIdx.x * 256 + threadIdx.x;   // 1M float4
    float4 v = ((const float4*)X)[i];
    ((uint2*)g_Xf)[i] = make_uint2(packh(v.x, v.y), packh(v.z, v.w));
}

// ---------------- prep: transpose W -> [mat][h*64+e][d], fp16 ----------------
__global__ __launch_bounds__(256) void prep_w(const float* __restrict__ Wq,
                                              const float* __restrict__ Wk,
                                              const float* __restrict__ Wv) {
    int z = blockIdx.z, mat = z >> 4, h = z & 15;
    const float* W = (mat == 0 ? Wq : (mat == 1 ? Wk : Wv)) + (size_t)h * 1024 * 64;
    __shared__ float t[32][33];
    int d0 = blockIdx.x * 32, e0 = blockIdx.y * 32;
    int tx = threadIdx.x, ty = threadIdx.y;
    #pragma unroll
    for (int k = 0; k < 4; k++)
        t[ty + 8 * k][tx] = W[(size_t)(d0 + ty + 8 * k) * 64 + e0 + tx];
    __syncthreads();
    __half* of = g_Wf + (size_t)mat * 1048576;
    #pragma unroll
    for (int k = 0; k < 4; k++) {
        int j = ty + 8 * k;
        of[(size_t)(h * 64 + e0 + j) * 1024 + d0 + tx] = __float2half(t[tx][j]);
    }
}

// ---------------- QKV GEMM: 128x128 CTA tile, fp16, k-chunk 64 ----------------
#define QS_STAGE 32768
#define QKV_SMEM (2 * QS_STAGE)

__device__ __forceinline__ void qkv_prefetch(uint32_t s0, int stile, int octile,
                                             int kc, int tid, const __half* Bf) {
    #pragma unroll
    for (int i = tid; i < 2048; i += 256) {
        int idx = i & 1023;
        int r = idx >> 3, c8 = idx & 7;
        bool isB = (i >= 1024);
        const __half* src = isB ? Bf : g_Xf;
        int gr = (isB ? octile : stile) * 128 + r;
        size_t g = (size_t)gr * 1024 + kc * 64 + c8 * 8;
        uint32_t d = s0 + (isB ? 16384u : 0u) + ((r >= 64) ? 8192u : 0u) + swoff(r & 63, c8);
        cpa16(d, src + g);
    }
}

__global__ __launch_bounds__(256, 2) void qkv_mm(const float* __restrict__ bq,
                                                 const float* __restrict__ bk,
                                                 const float* __restrict__ bv) {
    extern __shared__ __align__(16) __half smq[];
    uint32_t sb = smem_u32(smq);
    int tid = threadIdx.x, lane = tid & 31, wid = tid >> 5;
    int stile = blockIdx.x, octile = blockIdx.y, mat = blockIdx.z;
    int wm = wid >> 1, wn = wid & 1;   // 4x2 warps: 32 rows x 64 cols each
    int lm = lane & 15;

    const __half* Bf = g_Wf + (size_t)mat * 1048576;

    float C[2][8][4] = {};

    qkv_prefetch(sb, stile, octile, 0, tid, Bf);
    cpcommit();

    for (int kc = 0; kc < 16; kc++) {
        if (kc < 15) {
            qkv_prefetch(sb + ((kc + 1) & 1) * QS_STAGE, stile, octile, kc + 1, tid, Bf);
            cpcommit();
            cpwait1();
        } else {
            cpwait0();
        }
        __syncthreads();
        uint32_t sA = sb + (kc & 1) * QS_STAGE;
        uint32_t sB = sA + 16384;

        #pragma unroll
        for (int ks = 0; ks < 4; ks++) {
            uint32_t af[2][4];
            #pragma unroll
            for (int mt = 0; mt < 2; mt++) {
                int r = wm * 32 + mt * 16 + lm;
                uint32_t reg0 = (r >= 64) ? 8192u : 0u;
                int c8 = ks * 2 + (lane >> 4);
                ldsm_x4(sA + reg0 + swoff(r & 63, c8),
                        af[mt][0], af[mt][1], af[mt][2], af[mt][3]);
            }
            #pragma unroll
            for (int ntp = 0; ntp < 4; ntp++) {
                int rB = ntp * 16 + ((lane >> 4) << 3) + (lane & 7);
                int c8 = ks * 2 + ((lane >> 3) & 1);
                uint32_t regB = wn * 8192u;
                uint32_t h0, h1, h2, h3;
                ldsm_x4(sB + regB + swoff(rB, c8), h0, h1, h2, h3);
                #pragma unroll
                for (int mt = 0; mt < 2; mt++) {
                    mma16816(C[mt][2 * ntp],     af[mt], h0, h1);
                    mma16816(C[mt][2 * ntp + 1], af[mt], h2, h3);
                }
            }
        }
        __syncthreads();
    }

    const float* bias = (mat == 0 ? bq : (mat == 1 ? bk : bv));
    float scale = (mat == 0) ? 0.125f : 1.0f;
    __half* Df = (mat == 0 ? g_Qf : (mat == 1 ? g_Kf : g_Vf));
    #pragma unroll
    for (int mt = 0; mt < 2; mt++) {
        #pragma unroll
        for (int nt = 0; nt < 8; nt++) {
            int col = octile * 128 + wn * 64 + nt * 8 + 2 * (lane & 3);
            float b0 = __ldg(bias + col), b1 = __ldg(bias + col + 1);
            int hh = col >> 6, e = col & 63;
            #pragma unroll
            for (int hf = 0; hf < 2; hf++) {
                int row = stile * 128 + wm * 32 + mt * 16 + (lane >> 2) + 8 * hf;
                float v0 = (C[mt][nt][2 * hf + 0] + b0) * scale;
                float v1 = (C[mt][nt][2 * hf + 1] + b1) * scale;
                int b = row >> 11, s = row & 2047;
                size_t o = ((size_t)(b * 16 + hh) * 2048 + s) * 64 + e;
                *(uint32_t*)&Df[o] = packh(v0, v1);
            }
        }
    }
}

// ---------------- attention: fp16, three-way tile specialization ----------------
// smem: Q region0 @0, Q region1 @8192; stages @16384 + st*16384: K @+0, V @+8192
#define A_STAGE 16384
#define A_SMEM (16384 + 2 * A_STAGE)   // 48KB

__device__ __forceinline__ void attn_prefetch(uint32_t s0, int tid,
                                              const __half* Kf, const __half* Vf,
                                              bool full) {
    #pragma unroll
    for (int i = tid; i < 512; i += 256) {
        int r = i >> 3, c8 = i & 7;
        uint32_t d = swoff(r, c8);
        size_t g = (size_t)r * 64 + c8 * 8;
        cpa16(s0 + d, Kf + g);
        if (full) cpa16(s0 + 8192 + d, Vf + g);
    }
}

// S slice (16 rows x 16 cols), single fp16 term
__device__ __forceinline__ void compS(uint32_t sK, int k2, int lane,
                                      const uint32_t qf[4][4], float S[2][4]) {
    #pragma unroll
    for (int z = 0; z < 4; z++) { S[0][z] = 0.f; S[1][z] = 0.f; }
    #pragma unroll
    for (int ks = 0; ks < 4; ks++) {
        int row = k2 * 16 + ((lane >> 4) << 3) + (lane & 7);
        int c8 = ks * 2 + ((lane >> 3) & 1);
        uint32_t h0, h1, h2, h3;
        ldsm_x4(sK + swoff(row, c8), h0, h1, h2, h3);
        mma16816(S[0], qf[ks], h0, h1);
        mma16816(S[1], qf[ks], h2, h3);
    }
}

__global__ __launch_bounds__(256, 2) void attn(float* __restrict__ out) {
    extern __shared__ __align__(16) char sm[];
    uint32_t sb = smem_u32(sm);
    int tid = threadIdx.x, lane = tid & 31, w = tid >> 5;
    int bh = blockIdx.x >> 4, qt = 15 - (blockIdx.x & 15);   // heavy-first
    int b = bh >> 4, h = bh & 15;
    int lm = lane & 15;

    const __half* Qf  = g_Qf + ((size_t)bh * 2048 + qt * 128) * 64;
    const __half* Kfb = g_Kf + (size_t)bh * 2048 * 64;
    const __half* Vfb = g_Vf + (size_t)bh * 2048 * 64;

    // Q load (128x64 fp16, own region - never recycled)
    #pragma unroll
    for (int i = tid; i < 1024; i += 256) {
        int r = i >> 3, c8 = i & 7;
        uint32_t d = ((r >= 64) ? 8192u : 0u) + swoff(r & 63, c8);
        cpa16(sb + d, Qf + (size_t)r * 64 + c8 * 8);
    }
    cpcommit();

    int kmax = 2 * qt + 1;
    attn_prefetch(sb + 16384, tid, Kfb, Vfb, true);   // kt=0 always live
    cpcommit();

    cpwait1();          // Q group done
    __syncthreads();

    uint32_t qf[4][4];
    {
        int r = w * 16 + lm;
        uint32_t qreg = (r >= 64) ? 8192u : 0u;
        int rr = r & 63;
        #pragma unroll
        for (int ks = 0; ks < 4; ks++) {
            int c8 = ks * 2 + (lane >> 4);
            ldsm_x4(sb + qreg + swoff(rr, c8),
                    qf[ks][0], qf[ks][1], qf[ks][2], qf[ks][3]);
        }
    }

    float O[8][4] = {};
    float lsumA[2] = {}, lsumB[2] = {};   // split accumulator chains
    int rbase = qt * 128 + w * 16 + (lane >> 2);

    for (int kt = 0; kt < 32; kt++) {
        if (kt < 31) {
            size_t off = (size_t)(kt + 1) * 64 * 64;
            attn_prefetch(sb + 16384 + ((kt + 1) & 1) * A_STAGE, tid,
                          Kfb + off, Vfb + off, (kt + 1) <= kmax);
            cpcommit();
            cpwait1();
        } else {
            cpwait0();
        }
        __syncthreads();

        uint32_t sK = sb + 16384 + (kt & 1) * A_STAGE;
        uint32_t sV = sK + 8192;
        bool live = (kt <= kmax);
        bool diag = live && (kt >= 2 * qt);   // only tiles straddling the diagonal
        int cb = kt * 64 + 2 * (lane & 3);

        float Sc[2][4];
        compS(sK, 0, lane, qf, Sc);

        #pragma unroll
        for (int k2 = 0; k2 < 4; k2++) {
            // software pipeline: next slice's S MMAs overlap exp/PV of current
            float Sn[2][4];
            if (k2 < 3) compS(sK, k2 + 1, lane, qf, Sn);

            // ---- exp on MUFU + full-row lsum (mask only on diagonal tiles)
            #pragma unroll
            for (int ntl = 0; ntl < 2; ntl++) {
                #pragma unroll
                for (int hf = 0; hf < 2; hf++) {
                    float e0 = __expf(Sc[ntl][2 * hf + 0]);
                    float e1 = __expf(Sc[ntl][2 * hf + 1]);
                    lsumA[hf] += e0;
                    lsumB[hf] += e1;
                    Sc[ntl][2 * hf + 0] = e0;
                    Sc[ntl][2 * hf + 1] = e1;
                }
            }
            if (diag) {   // post-softmax tril mask, numerator only
                #pragma unroll
                for (int ntl = 0; ntl < 2; ntl++) {
                    int colg = cb + k2 * 16 + ntl * 8;
                    #pragma unroll
                    for (int hf = 0; hf < 2; hf++) {
                        int rg = rbase + 8 * hf;
                        if (colg     > rg) Sc[ntl][2 * hf + 0] = 0.f;
                        if (colg + 1 > rg) Sc[ntl][2 * hf + 1] = 0.f;
                    }
                }
            }
            // ---- PV for this 16-wide k-slice (single fp16 term, V double-buffered)
            if (live) {
                uint32_t ph[4];
                ph[0] = packh(Sc[0][0], Sc[0][1]);
                ph[1] = packh(Sc[0][2], Sc[0][3]);
                ph[2] = packh(Sc[1][0], Sc[1][1]);
                ph[3] = packh(Sc[1][2], Sc[1][3]);
                int row = k2 * 16 + lm;
                uint32_t vA[4];
                ldsm_x4t(sV + swoff(row, (lane >> 4)), vA[0], vA[1], vA[2], vA[3]);
                #pragma unroll
                for (int ntp = 0; ntp < 4; ntp++) {
                    uint32_t vB[4];
                    if (ntp < 3)
                        ldsm_x4t(sV + swoff(row, (ntp + 1) * 2 + (lane >> 4)),
                                 vB[0], vB[1], vB[2], vB[3]);
                    mma16816(O[2 * ntp],     ph, vA[0], vA[1]);
                    mma16816(O[2 * ntp + 1], ph, vA[2], vA[3]);
                    if (ntp < 3) {
                        #pragma unroll
                        for (int z = 0; z < 4; z++) vA[z] = vB[z];
                    }
                }
            }
            if (k2 < 3) {
                #pragma unroll
                for (int ntl = 0; ntl < 2; ntl++)
                    #pragma unroll
                    for (int z = 0; z < 4; z++) Sc[ntl][z] = Sn[ntl][z];
            }
        }
        __syncthreads();   // compute done before next prefetch overwrites other stage
    }

    // ---- row denominators: combine split chains + quad butterfly
    float lsum[2];
    #pragma unroll
    for (int hf = 0; hf < 2; hf++) {
        lsum[hf] = lsumA[hf] + lsumB[hf];
        lsum[hf] += __shfl_xor_sync(0xffffffffu, lsum[hf], 1);
        lsum[hf] += __shfl_xor_sync(0xffffffffu, lsum[hf], 2);
    }

    // ---- write out
    #pragma unroll
    for (int hf = 0; hf < 2; hf++) {
        float inv = 1.0f / lsum[hf];
        int rg = rbase + 8 * hf;
        float* ob = out + ((size_t)b * 2048 + rg) * 1024 + h * 64;
        #pragma unroll
        for (int nt = 0; nt < 8; nt++) {
            int c = nt * 8 + 2 * (lane & 3);
            *(float2*)&ob[c] = make_float2(O[nt][2 * hf] * inv, O[nt][2 * hf + 1] * inv);
        }
    }
}

extern "C" void kernel_launch(void* const* d_in, const int* in_sizes, int n_in,
                              void* d_out, int out_size) {
    const float* X  = (const float*)d_in[0];
    const float* Wq = (const float*)d_in[1];
    const float* bq = (const float*)d_in[2];
    const float* Wk = (const float*)d_in[3];
    const float* bk = (const float*)d_in[4];
    const float* Wv = (const float*)d_in[5];
    const float* bv = (const float*)d_in[6];

    cudaFuncSetAttribute(qkv_mm, cudaFuncAttributeMaxDynamicSharedMemorySize, QKV_SMEM);
    cudaFuncSetAttribute(attn,   cudaFuncAttributeMaxDynamicSharedMemorySize, A_SMEM);

    prep_x<<<4096, 256>>>(X);
    prep_w<<<dim3(32, 2, 48), dim3(32, 8)>>>(Wq, Wk, Wv);
    qkv_mm<<<dim3(32, 8, 3), 256, QKV_SMEM>>>(bq, bk, bv);
    attn<<<512, 256, A_SMEM>>>((float*)d_out);
}